// round 11
// baseline (speedup 1.0000x reference)
#include <cuda_runtime.h>
#include <math.h>

#define SEQ   4096
#define DIM   1024
#define NHEAD 16
#define HDIM  64
#define FHN   4
#define FDIM  256
#define CSZ   1024
#define NCH   4
#define BASE_LR_INV -6.90725517f

// ------------------------- scratch (static device globals, 16B aligned) ------------
__device__ __align__(16) float g_qkv[SEQ * 3 * DIM];
__device__ __align__(16) float g_qr[SEQ * DIM];
__device__ __align__(16) float g_kr[SEQ * DIM];
__device__ __align__(16) float g_fq[SEQ * DIM];
__device__ __align__(16) float g_fk[SEQ * DIM];
__device__ __align__(16) float g_fv[SEQ * DIM];
__device__ __align__(16) float g_lrbuf[SEQ * 12];
__device__ __align__(16) float g_ttt[SEQ * DIM];
__device__ __align__(16) float g_ao[SEQ * DIM];
__device__ __align__(16) float g_W0[FHN * FDIM * FDIM];
__device__ __align__(16) float g_W1[FHN * FDIM * FDIM];
__device__ __align__(16) float g_W2[FHN * FDIM * FDIM];
__device__ __align__(16) float g_W1c[NCH * FHN * FDIM * FDIM];
__device__ __align__(16) float g_gk[FHN * CSZ * FDIM];
__device__ __align__(16) float g_hk[FHN * CSZ * FDIM];
__device__ __align__(16) float g_qg[FHN * CSZ * FDIM];
__device__ __align__(16) float g_qm[FHN * CSZ * FDIM];
__device__ __align__(16) float g_dh[FHN * CSZ * FDIM];
__device__ __align__(16) float g_hid[FHN * CSZ * FDIM];
__device__ __align__(16) float g_dgk[FHN * CSZ * FDIM];
__device__ __align__(16) float g_dhk[FHN * CSZ * FDIM];
__device__ __align__(16) float g_vl1[FHN * CSZ * FDIM];
__device__ __align__(16) float g_hqa[NCH * FHN * CSZ * FDIM];

// ------------------------- side stream + events -------------------------
struct StreamCtx {
    cudaStream_t s2 = 0;
    cudaEvent_t e0 = 0, e1 = 0, e2 = 0, e3 = 0;
    cudaEvent_t ec[NCH] = {0, 0, 0, 0};
    bool ok = false;
    StreamCtx() {
        bool good = (cudaStreamCreateWithFlags(&s2, cudaStreamNonBlocking) == cudaSuccess);
        good = good && (cudaEventCreateWithFlags(&e0, cudaEventDisableTiming) == cudaSuccess);
        good = good && (cudaEventCreateWithFlags(&e1, cudaEventDisableTiming) == cudaSuccess);
        good = good && (cudaEventCreateWithFlags(&e2, cudaEventDisableTiming) == cudaSuccess);
        good = good && (cudaEventCreateWithFlags(&e3, cudaEventDisableTiming) == cudaSuccess);
        for (int i = 0; i < NCH; i++)
            good = good && (cudaEventCreateWithFlags(&ec[i], cudaEventDisableTiming) == cudaSuccess);
        ok = good;
    }
};
static StreamCtx g_sc;

// ------------------------- tf32 mma primitives -------------------------
__device__ __forceinline__ unsigned f2tf(float f)
{
    unsigned u;
    asm("cvt.rna.tf32.f32 %0, %1;" : "=r"(u) : "f"(f));
    return u;
}

__device__ __forceinline__ void mma8(float* c, const unsigned* a, const unsigned* b)
{
    asm volatile(
        "mma.sync.aligned.m16n8k8.row.col.f32.tf32.tf32.f32 "
        "{%0,%1,%2,%3},{%4,%5,%6,%7},{%8,%9},{%0,%1,%2,%3};"
        : "+f"(c[0]), "+f"(c[1]), "+f"(c[2]), "+f"(c[3])
        : "r"(a[0]), "r"(a[1]), "r"(a[2]), "r"(a[3]), "r"(b[0]), "r"(b[1]));
}

#define SSTR 136
#define BSTR 264

__device__ __forceinline__ void mma_block(
    const unsigned (*As)[SSTR], const unsigned (*Bs)[SSTR],
    float acc[4][4][4], int wm, int wn, int gid, int tig)
{
#pragma unroll
    for (int kh = 0; kh < 16; kh += 8) {
        unsigned a[4][4], b[4][2];
#pragma unroll
        for (int fm = 0; fm < 4; fm++) {
            int mb = wm * 64 + fm * 16;
            a[fm][0] = As[kh + tig][mb + gid];
            a[fm][1] = As[kh + tig][mb + gid + 8];
            a[fm][2] = As[kh + tig + 4][mb + gid];
            a[fm][3] = As[kh + tig + 4][mb + gid + 8];
        }
#pragma unroll
        for (int fn = 0; fn < 4; fn++) {
            int nb = wn * 32 + fn * 8;
            b[fn][0] = Bs[kh + tig][nb + gid];
            b[fn][1] = Bs[kh + tig + 4][nb + gid];
        }
#pragma unroll
        for (int fm = 0; fm < 4; fm++)
#pragma unroll
            for (int fn = 0; fn < 4; fn++) mma8(acc[fm][fn], a[fm], b[fn]);
    }
}

// ------------------------- generic tf32 GEMM (CTA 128x128) -------------------------
// mode: 0 store, 1 +=, 2 atomicAdd
__device__ __forceinline__ void gemm128(
    const float* __restrict__ A, const float* __restrict__ B, float* __restrict__ C,
    int m0, int n0, int K, int lda, int ldb, int ldc,
    bool transA, bool transB, int mode)
{
    __shared__ __align__(16) unsigned As[2][16][SSTR];
    __shared__ __align__(16) unsigned Bs[2][16][SSTR];
    const int tid = threadIdx.x;
    const int lane = tid & 31, warp = tid >> 5;
    const int wm = warp >> 2, wn = warp & 3;
    const int gid = lane >> 2, tig = lane & 3;

    float acc[4][4][4];
#pragma unroll
    for (int i = 0; i < 4; i++)
#pragma unroll
        for (int j = 0; j < 4; j++)
#pragma unroll
            for (int l = 0; l < 4; l++) acc[i][j][l] = 0.0f;

    float4 ar[2], br[2];
    auto fetchA = [&](int k0) {
#pragma unroll
        for (int s = 0; s < 2; s++) {
            int lin = tid + 256 * s;
            if (!transA) {
                int m = lin >> 2, kq = (lin & 3) * 4;
                ar[s] = *(const float4*)(A + (long)(m0 + m) * lda + (k0 + kq));
            } else {
                int k = lin >> 5, m4 = (lin & 31) * 4;
                ar[s] = *(const float4*)(A + (long)(k0 + k) * lda + (m0 + m4));
            }
        }
    };
    auto fetchB = [&](int k0) {
#pragma unroll
        for (int s = 0; s < 2; s++) {
            int lin = tid + 256 * s;
            if (transB) {
                int n = lin >> 2, kq = (lin & 3) * 4;
                br[s] = *(const float4*)(B + (long)(n0 + n) * ldb + (k0 + kq));
            } else {
                int k = lin >> 5, n4 = (lin & 31) * 4;
                br[s] = *(const float4*)(B + (long)(k0 + k) * ldb + (n0 + n4));
            }
        }
    };
    auto storeA = [&](int buf) {
#pragma unroll
        for (int s = 0; s < 2; s++) {
            int lin = tid + 256 * s;
            if (!transA) {
                int m = lin >> 2, kq = (lin & 3) * 4;
                As[buf][kq + 0][m] = f2tf(ar[s].x);
                As[buf][kq + 1][m] = f2tf(ar[s].y);
                As[buf][kq + 2][m] = f2tf(ar[s].z);
                As[buf][kq + 3][m] = f2tf(ar[s].w);
            } else {
                int k = lin >> 5, m4 = (lin & 31) * 4;
                uint4 u = {f2tf(ar[s].x), f2tf(ar[s].y), f2tf(ar[s].z), f2tf(ar[s].w)};
                *(uint4*)&As[buf][k][m4] = u;
            }
        }
    };
    auto storeB = [&](int buf) {
#pragma unroll
        for (int s = 0; s < 2; s++) {
            int lin = tid + 256 * s;
            if (transB) {
                int n = lin >> 2, kq = (lin & 3) * 4;
                Bs[buf][kq + 0][n] = f2tf(br[s].x);
                Bs[buf][kq + 1][n] = f2tf(br[s].y);
                Bs[buf][kq + 2][n] = f2tf(br[s].z);
                Bs[buf][kq + 3][n] = f2tf(br[s].w);
            } else {
                int k = lin >> 5, n4 = (lin & 31) * 4;
                uint4 u = {f2tf(br[s].x), f2tf(br[s].y), f2tf(br[s].z), f2tf(br[s].w)};
                *(uint4*)&Bs[buf][k][n4] = u;
            }
        }
    };

    const int nk = K >> 4;
    fetchA(0); fetchB(0); storeA(0); storeB(0);
    __syncthreads();
    for (int t = 0; t < nk; t++) {
        const int cur = t & 1;
        if (t + 1 < nk) { fetchA((t + 1) << 4); fetchB((t + 1) << 4); }
        mma_block(As[cur], Bs[cur], acc, wm, wn, gid, tig);
        if (t + 1 < nk) { storeA(cur ^ 1); storeB(cur ^ 1); }
        __syncthreads();
    }

#pragma unroll
    for (int fm = 0; fm < 4; fm++) {
        int r0 = m0 + wm * 64 + fm * 16 + gid;
#pragma unroll
        for (int fn = 0; fn < 4; fn++) {
            int cc = n0 + wn * 32 + fn * 8 + 2 * tig;
            float* p0 = C + (long)r0 * ldc + cc;
            float* p1 = C + (long)(r0 + 8) * ldc + cc;
            if (mode == 0) {
                p0[0] = acc[fm][fn][0]; p0[1] = acc[fm][fn][1];
                p1[0] = acc[fm][fn][2]; p1[1] = acc[fm][fn][3];
            } else if (mode == 1) {
                p0[0] += acc[fm][fn][0]; p0[1] += acc[fm][fn][1];
                p1[0] += acc[fm][fn][2]; p1[1] += acc[fm][fn][3];
            } else {
                atomicAdd(p0, acc[fm][fn][0]); atomicAdd(p0 + 1, acc[fm][fn][1]);
                atomicAdd(p1, acc[fm][fn][2]); atomicAdd(p1 + 1, acc[fm][fn][3]);
            }
        }
    }
}

// ------------------------- tf32 GEMM v3 (CTA 128x256, warp 64x64) -------------------
// A is [M,K] lda (no transA). transB: B [N,K] ldb ; !transB: B [K,N] ldb. Store only.
__device__ __forceinline__ void gemm256(
    const float* __restrict__ A, const float* __restrict__ B, float* __restrict__ C,
    int m0, int n0, int K, int lda, int ldb, int ldc, bool transB)
{
    __shared__ __align__(16) unsigned As[2][16][SSTR];
    __shared__ __align__(16) unsigned Bs[2][16][BSTR];
    const int tid = threadIdx.x;
    const int lane = tid & 31, warp = tid >> 5;
    const int wm = warp >> 2, wn = warp & 3;      // 2 x 4 warps, 64x64 each
    const int gid = lane >> 2, tig = lane & 3;

    float acc[4][8][4];
#pragma unroll
    for (int i = 0; i < 4; i++)
#pragma unroll
        for (int j = 0; j < 8; j++)
#pragma unroll
            for (int l = 0; l < 4; l++) acc[i][j][l] = 0.0f;

    float4 ar[2], br[4];
    auto fetchA = [&](int k0) {
#pragma unroll
        for (int s = 0; s < 2; s++) {
            int lin = tid + 256 * s;
            int m = lin >> 2, kq = (lin & 3) * 4;
            ar[s] = *(const float4*)(A + (long)(m0 + m) * lda + (k0 + kq));
        }
    };
    auto fetchB = [&](int k0) {
#pragma unroll
        for (int s = 0; s < 4; s++) {
            int lin = tid + 256 * s;
            if (transB) {
                int n = lin >> 2, kq = (lin & 3) * 4;
                br[s] = *(const float4*)(B + (long)(n0 + n) * ldb + (k0 + kq));
            } else {
                int k = lin >> 6, n4 = (lin & 63) * 4;
                br[s] = *(const float4*)(B + (long)(k0 + k) * ldb + (n0 + n4));
            }
        }
    };
    auto storeA = [&](int buf) {
#pragma unroll
        for (int s = 0; s < 2; s++) {
            int lin = tid + 256 * s;
            int m = lin >> 2, kq = (lin & 3) * 4;
            As[buf][kq + 0][m] = f2tf(ar[s].x);
            As[buf][kq + 1][m] = f2tf(ar[s].y);
            As[buf][kq + 2][m] = f2tf(ar[s].z);
            As[buf][kq + 3][m] = f2tf(ar[s].w);
        }
    };
    auto storeB = [&](int buf) {
#pragma unroll
        for (int s = 0; s < 4; s++) {
            int lin = tid + 256 * s;
            if (transB) {
                int n = lin >> 2, kq = (lin & 3) * 4;
                Bs[buf][kq + 0][n] = f2tf(br[s].x);
                Bs[buf][kq + 1][n] = f2tf(br[s].y);
                Bs[buf][kq + 2][n] = f2tf(br[s].z);
                Bs[buf][kq + 3][n] = f2tf(br[s].w);
            } else {
                int k = lin >> 6, n4 = (lin & 63) * 4;
                uint4 u = {f2tf(br[s].x), f2tf(br[s].y), f2tf(br[s].z), f2tf(br[s].w)};
                *(uint4*)&Bs[buf][k][n4] = u;
            }
        }
    };

    const int nk = K >> 4;
    fetchA(0); fetchB(0); storeA(0); storeB(0);
    __syncthreads();
    for (int t = 0; t < nk; t++) {
        const int cur = t & 1;
        if (t + 1 < nk) { fetchA((t + 1) << 4); fetchB((t + 1) << 4); }
#pragma unroll
        for (int kh = 0; kh < 16; kh += 8) {
            unsigned a[4][4], b[8][2];
#pragma unroll
            for (int fm = 0; fm < 4; fm++) {
                int mb = wm * 64 + fm * 16;
                a[fm][0] = As[cur][kh + tig][mb + gid];
                a[fm][1] = As[cur][kh + tig][mb + gid + 8];
                a[fm][2] = As[cur][kh + tig + 4][mb + gid];
                a[fm][3] = As[cur][kh + tig + 4][mb + gid + 8];
            }
#pragma unroll
            for (int fn = 0; fn < 8; fn++) {
                int nb = wn * 64 + fn * 8;
                b[fn][0] = Bs[cur][kh + tig][nb + gid];
                b[fn][1] = Bs[cur][kh + tig + 4][nb + gid];
            }
#pragma unroll
            for (int fm = 0; fm < 4; fm++)
#pragma unroll
                for (int fn = 0; fn < 8; fn++) mma8(acc[fm][fn], a[fm], b[fn]);
        }
        if (t + 1 < nk) { storeA(cur ^ 1); storeB(cur ^ 1); }
        __syncthreads();
    }

#pragma unroll
    for (int fm = 0; fm < 4; fm++) {
        int r0 = m0 + wm * 64 + fm * 16 + gid;
#pragma unroll
        for (int fn = 0; fn < 8; fn++) {
            int cc = n0 + wn * 64 + fn * 8 + 2 * tig;
            float* p0 = C + (long)r0 * ldc + cc;
            float* p1 = C + (long)(r0 + 8) * ldc + cc;
            p0[0] = acc[fm][fn][0]; p0[1] = acc[fm][fn][1];
            p1[0] = acc[fm][fn][2]; p1[1] = acc[fm][fn][3];
        }
    }
}

// ------------------------- helpers -------------------------
__device__ __forceinline__ float sigmoidf_(float x) { return 1.0f / (1.0f + expf(-x)); }
__device__ __forceinline__ float warp_sum(float v)
{
#pragma unroll
    for (int o = 16; o > 0; o >>= 1) v += __shfl_xor_sync(0xffffffffu, v, o);
    return v;
}

// ------------------------- kernels -------------------------
__global__ void k_initW(const float* __restrict__ w0, const float* __restrict__ w1,
                        const float* __restrict__ w2)
{
    int i = blockIdx.x * blockDim.x + threadIdx.x;
    if (i < FHN * FDIM * FDIM) { g_W0[i] = w0[i]; g_W1[i] = w1[i]; g_W2[i] = w2[i]; }
}

__global__ __launch_bounds__(256) void k_gemm_qkv(const float* __restrict__ x,
                                                  const float* __restrict__ Wqkv)
{
    gemm256(x, Wqkv, g_qkv, blockIdx.y * 128, blockIdx.x * 256,
            DIM, DIM, DIM, 3 * DIM, true);
}

__global__ __launch_bounds__(128) void k_lr(const float* __restrict__ x,
                                            const float* __restrict__ Wlr,
                                            const float* __restrict__ blr)
{
    __shared__ __align__(16) float sx[DIM];
    int s = blockIdx.x;
    for (int i = threadIdx.x; i < DIM; i += 128) sx[i] = x[(long)s * DIM + i];
    __syncthreads();
    int w = threadIdx.x >> 5, lane = threadIdx.x & 31;
    for (int j = w; j < 12; j += 4) {
        float sum = 0.0f;
        for (int d = lane; d < DIM; d += 32) sum += sx[d] * Wlr[(long)j * DIM + d];
        sum = warp_sum(sum);
        if (lane == 0) {
            float v = sum + blr[j] + BASE_LR_INV;
            g_lrbuf[s * 12 + j] = (v > 20.0f) ? v : log1pf(expf(v));
        }
    }
}

// RMSNorm(q,k) + fw inputs + fv + RoPE — float4 vectorized
__global__ __launch_bounds__(256) void k_post(const float* __restrict__ qnw,
                                              const float* __restrict__ knw,
                                              const float* __restrict__ qks,
                                              const float* __restrict__ qko)
{
    __shared__ __align__(16) float s_q[DIM];
    __shared__ __align__(16) float s_k[DIM];
    __shared__ __align__(16) float s_cs[32];
    __shared__ __align__(16) float s_sn[32];
    __shared__ float s_w2[8][2];
    __shared__ float s_hq[8], s_hk[8];
    __shared__ float s_fin[2];

    int s = blockIdx.x, t = threadIdx.x, lane = t & 31, w = t >> 5;
    const float* qrow = g_qkv + (long)s * 3072;

    if (t < 32) {
        double inv = exp(-((double)(2 * t) / 64.0) * log(500000.0));
        double a = (double)s * inv;
        const double tw = 6.283185307179586476925286766559;
        a -= floor(a / tw) * tw;
        s_cs[t] = (float)cos(a);
        s_sn[t] = (float)sin(a);
    }

    int d = 4 * t;
    float4 q4 = *(const float4*)(qrow + d);
    float4 k4 = *(const float4*)(qrow + DIM + d);
    float4 v4 = *(const float4*)(qrow + 2 * DIM + d);

    float sq = q4.x * q4.x + q4.y * q4.y + q4.z * q4.z + q4.w * q4.w;
    float sk = k4.x * k4.x + k4.y * k4.y + k4.z * k4.z + k4.w * k4.w;
    sq = warp_sum(sq); sk = warp_sum(sk);
    if (lane == 0) { s_w2[w][0] = sq; s_w2[w][1] = sk; }
    __syncthreads();
    if (t < 2) {
        float a = 0.0f;
#pragma unroll
        for (int i = 0; i < 8; i++) a += s_w2[i][t];
        s_fin[t] = a;
    }
    __syncthreads();
    float rq = rsqrtf(s_fin[0] / 1024.0f + 1e-5f);
    float rk = rsqrtf(s_fin[1] / 1024.0f + 1e-5f);

    float4 qw4 = *(const float4*)(qnw + d);
    float4 kw4 = *(const float4*)(knw + d);
    float qn[4] = {q4.x * rq * qw4.x, q4.y * rq * qw4.y, q4.z * rq * qw4.z, q4.w * rq * qw4.w};
    float kn[4] = {k4.x * rk * kw4.x, k4.y * rk * kw4.y, k4.z * rk * kw4.z, k4.w * rk * kw4.w};
    *(float4*)&s_q[d] = make_float4(qn[0], qn[1], qn[2], qn[3]);
    *(float4*)&s_k[d] = make_float4(kn[0], kn[1], kn[2], kn[3]);

    float4 qsA = *(const float4*)(qks + 2 * d);
    float4 qsB = *(const float4*)(qks + 2 * d + 4);
    float4 qoA = *(const float4*)(qko + 2 * d);
    float4 qoB = *(const float4*)(qko + 2 * d + 4);
    float scq[4] = {qsA.x, qsA.z, qsB.x, qsB.z};
    float sck[4] = {qsA.y, qsA.w, qsB.y, qsB.w};
    float ofq[4] = {qoA.x, qoA.z, qoB.x, qoB.z};
    float ofk[4] = {qoA.y, qoA.w, qoB.y, qoB.w};

    float fq[4], fk[4], fv[4];
    float sqq = 0.0f, skk = 0.0f;
    float vvv[4] = {v4.x, v4.y, v4.z, v4.w};
#pragma unroll
    for (int j = 0; j < 4; j++) {
        fq[j] = qn[j] * sigmoidf_(qn[j]) * scq[j] + ofq[j];
        fk[j] = kn[j] * sigmoidf_(kn[j]) * sck[j] + ofk[j];
        fv[j] = vvv[j] * sigmoidf_(vvv[j]);
        sqq += fq[j] * fq[j];
        skk += fk[j] * fk[j];
    }
    *(float4*)&g_fv[(long)s * DIM + d] = make_float4(fv[0], fv[1], fv[2], fv[3]);

    sqq = warp_sum(sqq); skk = warp_sum(skk);
    if (lane == 0) { s_hq[w] = sqq; s_hk[w] = skk; }
    __syncthreads();
    float rfq = rsqrtf(s_hq[w & ~1] + s_hq[w | 1] + 1e-6f);
    float rfk = rsqrtf(s_hk[w & ~1] + s_hk[w | 1] + 1e-6f);
#pragma unroll
    for (int j = 0; j < 4; j++) { fq[j] *= rfq; fk[j] *= rfk; }
    *(float4*)&g_fq[(long)s * DIM + d] = make_float4(fq[0], fq[1], fq[2], fq[3]);
    *(float4*)&g_fk[(long)s * DIM + d] = make_float4(fk[0], fk[1], fk[2], fk[3]);

    int r = d & 63, ip = d & 31;
    float4 cs = *(float4*)&s_cs[ip];
    float4 sn = *(float4*)&s_sn[ip];
    float4 xq = *(float4*)&s_q[d], xpq = *(float4*)&s_q[d ^ 32];
    float4 xk = *(float4*)&s_k[d], xpk = *(float4*)&s_k[d ^ 32];
    float sgn = (r < 32) ? -1.0f : 1.0f;
    *(float4*)&g_qr[(long)s * DIM + d] = make_float4(
        xq.x * cs.x + sgn * xpq.x * sn.x, xq.y * cs.y + sgn * xpq.y * sn.y,
        xq.z * cs.z + sgn * xpq.z * sn.z, xq.w * cs.w + sgn * xpq.w * sn.w);
    *(float4*)&g_kr[(long)s * DIM + d] = make_float4(
        xk.x * cs.x + sgn * xpk.x * sn.x, xk.y * cs.y + sgn * xpk.y * sn.y,
        xk.z * cs.z + sgn * xpk.z * sn.z, xk.w * cs.w + sgn * xpk.w * sn.w);
}

// TTT stage 1: gk,hk,qg,qm,dh GEMMs (gemm256, grid 1x8x24) + W1 snapshot
__global__ __launch_bounds__(256) void k_ttt1(int c)
{
    int z = blockIdx.z;
    int h = z / 6, op = z - h * 6;
    if (op == 5) {  // snapshot W1 (8 CTAs: blockIdx.y 0..7, blockIdx.x == 0)
        int cta = blockIdx.y;
        const float4* src = (const float4*)(g_W1 + h * FDIM * FDIM);
        float4* dst = (float4*)(g_W1c + ((long)c * FHN + h) * FDIM * FDIM);
#pragma unroll
        for (int j = 0; j < 8; j++) {
            int idx = j * 2048 + cta * 256 + threadIdx.x;
            dst[idx] = src[idx];
        }
        return;
    }
    long choff = (long)c * CSZ * DIM + h * FDIM;
    const float* A; const float* B; float* Cp; bool tb = true;
    switch (op) {
        case 0: A = g_fk + choff; B = g_W0 + h * FDIM * FDIM; Cp = g_gk + (long)h * CSZ * FDIM; break;
        case 1: A = g_fk + choff; B = g_W2 + h * FDIM * FDIM; Cp = g_hk + (long)h * CSZ * FDIM; break;
        case 2: A = g_fq + choff; B = g_W0 + h * FDIM * FDIM; Cp = g_qg + (long)h * CSZ * FDIM; break;
        case 3: A = g_fq + choff; B = g_W2 + h * FDIM * FDIM; Cp = g_qm + (long)h * CSZ * FDIM; break;
        default: A = g_fv + choff; B = g_W1 + h * FDIM * FDIM;
                Cp = g_dh + (long)h * CSZ * FDIM; tb = false; break;
    }
    gemm256(A, B, Cp, blockIdx.y * 128, 0, FDIM, DIM, FDIM, FDIM, tb);
}

// TTT stage 2: elementwise activations / lr scaling — float4 vectorized
__global__ __launch_bounds__(256) void k_ttt2(int c)
{
    long idx = ((long)blockIdx.x * 256 + threadIdx.x) * 4;
    int h = (int)(idx >> 18);
    int rem = (int)(idx & 262143);
    int t = rem >> 8;
    int e = rem & 255;
    int sg = c * CSZ + t;
    float l0 = g_lrbuf[sg * 12 + h];
    float l1 = g_lrbuf[sg * 12 + 4 + h];
    float l2 = g_lrbuf[sg * 12 + 8 + h];
    float4 gk4 = *(const float4*)&g_gk[idx];
    float4 hk4 = *(const float4*)&g_hk[idx];
    float4 dh4 = *(const float4*)&g_dh[idx];
    float4 qg4 = *(const float4*)&g_qg[idx];
    float4 qm4 = *(const float4*)&g_qm[idx];
    float4 fv4 = *(const float4*)&g_fv[(long)sg * DIM + h * FDIM + e];
    float gk[4] = {gk4.x, gk4.y, gk4.z, gk4.w};
    float hk[4] = {hk4.x, hk4.y, hk4.z, hk4.w};
    float dh[4] = {dh4.x, dh4.y, dh4.z, dh4.w};
    float qg[4] = {qg4.x, qg4.y, qg4.z, qg4.w};
    float qm[4] = {qm4.x, qm4.y, qm4.z, qm4.w};
    float fv[4] = {fv4.x, fv4.y, fv4.z, fv4.w};
    float hq[4], hid[4], dgk[4], dhk[4], vl1[4];
#pragma unroll
    for (int j = 0; j < 4; j++) {
        float sgm = sigmoidf_(gk[j]);
        float sil = gk[j] * sgm;
        hq[j] = qg[j] * sigmoidf_(qg[j]) * qm[j];
        hid[j] = sil * hk[j];
        float dsil = sgm * (1.0f + gk[j] * (1.0f - sgm));
        dgk[j] = dh[j] * hk[j] * dsil * l0;
        dhk[j] = dh[j] * sil * l2;
        vl1[j] = fv[j] * l1;
    }
    *(float4*)&g_hqa[(long)c * FHN * CSZ * FDIM + idx] = make_float4(hq[0], hq[1], hq[2], hq[3]);
    *(float4*)&g_hid[idx] = make_float4(hid[0], hid[1], hid[2], hid[3]);
    *(float4*)&g_dgk[idx] = make_float4(dgk[0], dgk[1], dgk[2], dgk[3]);
    *(float4*)&g_dhk[idx] = make_float4(dhk[0], dhk[1], dhk[2], dhk[3]);
    *(float4*)&g_vl1[idx] = make_float4(vl1[0], vl1[1], vl1[2], vl1[3]);
}

// TTT stage 4: rank-CSZ weight updates, split-K 8x with atomic accumulate
__global__ __launch_bounds__(256) void k_ttt4(int c)
{
    int z = blockIdx.z;
    int h = z / 24;
    int r = z - h * 24;
    int op = r >> 3, sl = r & 7;
    long koff = (long)c * CSZ * DIM + h * FDIM;
    const float* A; const float* B; float* Cp; int lda, ldb;
    switch (op) {
        case 0: A = g_vl1 + (long)h * CSZ * FDIM; B = g_hid + (long)h * CSZ * FDIM;
                Cp = g_W1 + h * FDIM * FDIM; lda = FDIM; ldb = FDIM; break;
        case 1: A = g_dgk + (long)h * CSZ * FDIM; B = g_fk + koff;
                Cp = g_W0 + h * FDIM * FDIM; lda = FDIM; ldb = DIM; break;
        default: A = g_dhk + (long)h * CSZ * FDIM; B = g_fk + koff;
                Cp = g_W2 + h * FDIM * FDIM; lda = FDIM; ldb = DIM; break;
    }
    A += (long)sl * 128 * lda;
    B += (long)sl * 128 * ldb;
    gemm128(A, B, Cp, blockIdx.y * 128, blockIdx.x * 128, 128, lda, ldb, FDIM, true, false, 2);
}

// Deferred TTT stage 3, one chunk (runs on side stream in loop shadow)
__global__ __launch_bounds__(256) void k_ttt3c(int c)
{
    int h = blockIdx.z;
    gemm128(g_hqa + ((long)c * FHN + h) * CSZ * FDIM,
            g_W1c + ((long)c * FHN + h) * FDIM * FDIM,
            g_ttt + (long)c * CSZ * DIM + h * FDIM,
            blockIdx.y * 128, blockIdx.x * 128, FDIM, FDIM, FDIM, DIM, false, true, 0);
}

// ------------------------- tf32 flash attention -------------------------
#define SQSTR 68
#define SKSTR 68
#define SVSTR 72
#define ATTN_SMEM ((128 * SQSTR + 64 * SKSTR + 64 * SVSTR) * 4)

__global__ __launch_bounds__(256) void k_attn()
{
    extern __shared__ __align__(16) float sm[];
    float* sQP = sm;
    unsigned* sK = (unsigned*)(sm + 128 * SQSTR);
    unsigned* sV = (unsigned*)(sm + 128 * SQSTR + 64 * SKSTR);

    const int h = blockIdx.y, qt = blockIdx.x;
    const int p0 = qt * 128;
    const int tid = threadIdx.x;
    const int lane = tid & 31, warp = tid >> 5;
    const int gid = lane >> 2, tig = lane & 3;

#pragma unroll
    for (int s = 0; s < 8; s++) {
        int lin = tid + 256 * s;
        int r = lin >> 4, c4 = (lin & 15) * 4;
        *(float4*)&sQP[r * SQSTR + c4] =
            *(const float4*)&g_qr[(long)(p0 + r) * DIM + h * HDIM + c4];
    }
    __syncthreads();

    const int rq = warp * 16 + gid;
    unsigned qa[8][4];
#pragma unroll
    for (int kb = 0; kb < 8; kb++) {
        qa[kb][0] = f2tf(0.125f * sQP[rq * SQSTR + kb * 8 + tig]);
        qa[kb][1] = f2tf(0.125f * sQP[(rq + 8) * SQSTR + kb * 8 + tig]);
        qa[kb][2] = f2tf(0.125f * sQP[rq * SQSTR + kb * 8 + tig + 4]);
        qa[kb][3] = f2tf(0.125f * sQP[(rq + 8) * SQSTR + kb * 8 + tig + 4]);
    }

    float o[8][4];
#pragma unroll
    for (int fn = 0; fn < 8; fn++)
#pragma unroll
        for (int j = 0; j < 4; j++) o[fn][j] = 0.0f;
    float mrow0 = -1e30f, mrow1 = -1e30f, lsum0 = 0.0f, lsum1 = 0.0f;

    const int ktlo = (qt >= 8) ? 2 * qt - 16 : 0;
    const int kthi = 2 * qt + 1;
    const int prow0 = p0 + warp * 16 + gid;
    const int prow1 = prow0 + 8;

    for (int kt = ktlo; kt <= kthi; kt++) {
        __syncthreads();
#pragma unroll
        for (int s = 0; s < 4; s++) {
            int lin = tid + 256 * s;
            int r = lin >> 4, c4 = (lin & 15) * 4;
            float4 kv = *(const float4*)&g_kr[(long)(kt * 64 + r) * DIM + h * HDIM + c4];
            uint4 ku = {f2tf(kv.x), f2tf(kv.y), f2tf(kv.z), f2tf(kv.w)};
            *(uint4*)&sK[r * SKSTR + c4] = ku;
            float4 vv = *(const float4*)&g_qkv[(long)(kt * 64 + r) * 3072 + 2048 + h * HDIM + c4];
            uint4 vu = {f2tf(vv.x), f2tf(vv.y), f2tf(vv.z), f2tf(vv.w)};
            *(uint4*)&sV[r * SVSTR + c4] = vu;
        }
        __syncthreads();

        float sc[8][4];
#pragma unroll
        for (int fn = 0; fn < 8; fn++)
#pragma unroll
            for (int j = 0; j < 4; j++) sc[fn][j] = 0.0f;
#pragma unroll
        for (int kb = 0; kb < 8; kb++) {
#pragma unroll
            for (int fn = 0; fn < 8; fn++) {
                unsigned b[2];
                b[0] = sK[(fn * 8 + gid) * SKSTR + kb * 8 + tig];
                b[1] = sK[(fn * 8 + gid) * SKSTR + kb * 8 + tig + 4];
                mma8(sc[fn], qa[kb], b);
            }
        }
#pragma unroll
        for (int fn = 0; fn < 8; fn++) {
            int g0 = kt * 64 + fn * 8 + 2 * tig;
            int g1 = g0 + 1;
            sc[fn][0] = (g0 > prow0 - 1024 && g0 <= prow0) ? sc[fn][0] : -1e30f;
            sc[fn][1] = (g1 > prow0 - 1024 && g1 <= prow0) ? sc[fn][1] : -1e30f;
            sc[fn][2] = (g0 > prow1 - 1024 && g0 <= prow1) ? sc[fn][2] : -1e30f;
            sc[fn][3] = (g1 > prow1 - 1024 && g1 <= prow1) ? sc[fn][3] : -1e30f;
        }
        float t0 = -1e30f, t1 = -1e30f;
#pragma unroll
        for (int fn = 0; fn < 8; fn++) {
            t0 = fmaxf(t0, fmaxf(sc[fn][0], sc[fn][1]));
            t1 = fmaxf(t1, fmaxf(sc[fn][2], sc[fn][3]));
        }
#pragma unroll
        for (int off = 1; off < 4; off <<= 1) {
            t0 = fmaxf(t0, __shfl_xor_sync(0xffffffffu, t0, off));
            t1 = fmaxf(t1, __shfl_xor_sync(0xffffffffu, t1, off));
        }
        float mn0 = fmaxf(mrow0, t0), mn1 = fmaxf(mrow1, t1);
        float al0 = expf(mrow0 - mn0), al1 = expf(mrow1 - mn1);
        float mc0 = fmaxf(mn0, -1e20f), mc1 = fmaxf(mn1, -1e20f);
        float rs0 = 0.0f, rs1 = 0.0f;
#pragma unroll
        for (int fn = 0; fn < 8; fn++) {
            sc[fn][0] = expf(sc[fn][0] - mc0);
            sc[fn][1] = expf(sc[fn][1] - mc0);
            sc[fn][2] = expf(sc[fn][2] - mc1);
            sc[fn][3] = expf(sc[fn][3] - mc1);
            rs0 += sc[fn][0] + sc[fn][1];
            rs1 += sc[fn][2] + sc[fn][3];
        }
#pragma unroll
        for (int off = 1; off < 4; off <<= 1) {
            rs0 += __shfl_xor_sync(0xffffffffu, rs0, off);
            rs1 += __shfl_xor_sync(0xffffffffu, rs1, off);
        }
        lsum0 = lsum0 * al0 + rs0;
        lsum1 = lsum1 * al1 + rs1;
        mrow0 = mn0; mrow1 = mn1;
#pragma unroll
        for (int fn = 0; fn < 8; fn++) {
            o[fn][0] *= al0; o[fn][1] *= al0;
            o[fn][2] *= al1; o[fn][3] *= al1;
        }
        const int rp = warp * 16 + gid;
#pragma unroll
        for (int fn = 0; fn < 8; fn++) {
            sQP[rp * SQSTR + fn * 8 + 2 * tig]           = sc[fn][0];
            sQP[rp * SQSTR + fn * 8 + 2 * tig + 1]       = sc[fn][1];
            sQP[(rp + 8) * SQSTR + fn * 8 + 2 * tig]     = sc[fn][2];
            sQP[(rp + 8) * SQSTR + fn * 8 + 2 * tig + 1] = sc[fn][3];
        }
        __syncwarp();
#pragma unroll
        for (int kb = 0; kb < 8; kb++) {
            unsigned pa[4];
            pa[0] = f2tf(sQP[rp * SQSTR + kb * 8 + tig]);
            pa[1] = f2tf(sQP[(rp + 8) * SQSTR + kb * 8 + tig]);
            pa[2] = f2tf(sQP[rp * SQSTR + kb * 8 + tig + 4]);
            pa[3] = f2tf(sQP[(rp + 8) * SQSTR + kb * 8 + tig + 4]);
#pragma unroll
            for (int fn = 0; fn < 8; fn++) {
                unsigned b[2];
                b[0] = sV[(kb * 8 + tig) * SVSTR + fn * 8 + gid];
                b[1] = sV[(kb * 8 + tig + 4) * SVSTR + fn * 8 + gid];
                mma8(o[fn], pa, b);
            }
        }
        __syncwarp();
    }

    float inv0 = 1.0f / lsum0, inv1 = 1.0f / lsum1;
#pragma unroll
    for (int fn = 0; fn < 8; fn++) {
        int cc = h * HDIM + fn * 8 + 2 * tig;
        g_ao[(long)prow0 * DIM + cc]     = o[fn][0] * inv0;
        g_ao[(long)prow0 * DIM + cc + 1] = o[fn][1] * inv0;
        g_ao[(long)prow1 * DIM + cc]     = o[fn][2] * inv1;
        g_ao[(long)prow1 * DIM + cc + 1] = o[fn][3] * inv1;
    }
}

// TTT rmsnorm + add into g_ao (float4)
__global__ __launch_bounds__(256) void k_comb(const float* __restrict__ tnw)
{
    __shared__ float s_h[8];
    int s = blockIdx.x, t = threadIdx.x, lane = t & 31, w = t >> 5;
    int d = 4 * t;
    float4 v4 = *(const float4*)&g_ttt[(long)s * DIM + d];
    float p = v4.x * v4.x + v4.y * v4.y + v4.z * v4.z + v4.w * v4.w;
    p = warp_sum(p);
    if (lane == 0) s_h[w] = p;
    __syncthreads();
    float r = rsqrtf((s_h[w & ~1] + s_h[w | 1]) / 256.0f + 1e-5f);
    float4 w4 = *(const float4*)&tnw[d & 255];
    float4 a4 = *(float4*)&g_ao[(long)s * DIM + d];
    a4.x += v4.x * r * w4.x; a4.y += v4.y * r * w4.y;
    a4.z += v4.z * r * w4.z; a4.w += v4.w * r * w4.w;
    *(float4*)&g_ao[(long)s * DIM + d] = a4;
}

__global__ __launch_bounds__(256) void k_gemm_out(const float* __restrict__ Wo,
                                                 float* __restrict__ out)
{
    gemm128(g_ao, Wo, out, blockIdx.y * 128, blockIdx.x * 128,
            DIM, DIM, DIM, DIM, false, true, 0);
}

// ------------------------- launch -------------------------
extern "C" void kernel_launch(void* const* d_in, const int* in_sizes, int n_in,
                              void* d_out, int out_size)
{
    const float* x    = (const float*)d_in[0];
    const float* Wqkv = (const float*)d_in[1];
    const float* qnw  = (const float*)d_in[2];
    const float* knw  = (const float*)d_in[3];
    const float* Wo   = (const float*)d_in[4];
    const float* w0   = (const float*)d_in[5];
    const float* w1   = (const float*)d_in[6];
    const float* w2   = (const float*)d_in[7];
    const float* Wlr  = (const float*)d_in[8];
    const float* blr  = (const float*)d_in[9];
    const float* qks  = (const float*)d_in[10];
    const float* qko  = (const float*)d_in[11];
    const float* tnw  = (const float*)d_in[12];
    float* out = (float*)d_out;

    cudaFuncSetAttribute(k_attn, cudaFuncAttributeMaxDynamicSharedMemorySize, ATTN_SMEM);

    cudaStream_t s2 = g_sc.s2;

    if (g_sc.ok) {
        cudaEventRecord(g_sc.e0, 0);
        cudaStreamWaitEvent(s2, g_sc.e0, 0);
        k_initW<<<1024, 256, 0, s2>>>(w0, w1, w2);
        k_lr<<<4096, 128, 0, s2>>>(x, Wlr, blr);
        cudaEventRecord(g_sc.e1, s2);

        k_gemm_qkv<<<dim3(12, 32), 256>>>(x, Wqkv);
        k_post<<<4096, 256>>>(qnw, knw, qks, qko);

        cudaEventRecord(g_sc.e2, 0);
        cudaStreamWaitEvent(s2, g_sc.e2, 0);
        k_attn<<<dim3(32, NHEAD), 256, ATTN_SMEM, s2>>>();

        cudaStreamWaitEvent(0, g_sc.e1, 0);
        for (int c = 0; c < NCH; c++) {
            k_ttt1<<<dim3(1, 8, 24), 256>>>(c);
            k_ttt2<<<1024, 256>>>(c);
            cudaEventRecord(g_sc.ec[c], 0);
            cudaStreamWaitEvent(s2, g_sc.ec[c], 0);
            k_ttt3c<<<dim3(2, 8, 4), 256, 0, s2>>>(c);
            k_ttt4<<<dim3(2, 2, 96), 256>>>(c);
        }
        cudaEventRecord(g_sc.e3, s2);

        cudaStreamWaitEvent(0, g_sc.e3, 0);
        k_comb<<<4096, 256>>>(tnw);
        k_gemm_out<<<dim3(8, 32), 256>>>(Wo, out);
    } else {
        k_initW<<<1024, 256>>>(w0, w1, w2);
        k_gemm_qkv<<<dim3(12, 32), 256>>>(x, Wqkv);
        k_lr<<<4096, 128>>>(x, Wlr, blr);
        k_post<<<4096, 256>>>(qnw, knw, qks, qko);
        for (int c = 0; c < NCH; c++) {
            k_ttt1<<<dim3(1, 8, 24), 256>>>(c);
            k_ttt2<<<1024, 256>>>(c);
            k_ttt3c<<<dim3(2, 8, 4), 256>>>(c);
            k_ttt4<<<dim3(2, 2, 96), 256>>>(c);
        }
        k_attn<<<dim3(32, NHEAD), 256, ATTN_SMEM>>>();
        k_comb<<<4096, 256>>>(tnw);
        k_gemm_out<<<dim3(8, 32), 256>>>(Wo, out);
    }
}

// round 12
// speedup vs baseline: 1.0036x; 1.0036x over previous
#include <cuda_runtime.h>
#include <math.h>

#define SEQ   4096
#define DIM   1024
#define NHEAD 16
#define HDIM  64
#define FHN   4
#define FDIM  256
#define CSZ   1024
#define NCH   4
#define BASE_LR_INV -6.90725517f

// ------------------------- scratch (static device globals, 16B aligned) ------------
__device__ __align__(16) float g_qkv[SEQ * 3 * DIM];
__device__ __align__(16) float g_qr[SEQ * DIM];
__device__ __align__(16) float g_kr[SEQ * DIM];
__device__ __align__(16) float g_fq[SEQ * DIM];
__device__ __align__(16) float g_fk[SEQ * DIM];
__device__ __align__(16) float g_fv[SEQ * DIM];
__device__ __align__(16) float g_lrbuf[SEQ * 12];
__device__ __align__(16) float g_ttt[SEQ * DIM];
__device__ __align__(16) float g_ao[SEQ * DIM];
__device__ __align__(16) float g_rms[SEQ * FHN];
__device__ __align__(16) float g_W0[FHN * FDIM * FDIM];
__device__ __align__(16) float g_W1[FHN * FDIM * FDIM];
__device__ __align__(16) float g_W2[FHN * FDIM * FDIM];
__device__ __align__(16) float g_W1c[NCH * FHN * FDIM * FDIM];
__device__ __align__(16) float g_gk[FHN * CSZ * FDIM];
__device__ __align__(16) float g_hk[FHN * CSZ * FDIM];
__device__ __align__(16) float g_qg[FHN * CSZ * FDIM];
__device__ __align__(16) float g_qm[FHN * CSZ * FDIM];
__device__ __align__(16) float g_dh[FHN * CSZ * FDIM];
__device__ __align__(16) float g_hid[FHN * CSZ * FDIM];
__device__ __align__(16) float g_dgk[FHN * CSZ * FDIM];
__device__ __align__(16) float g_dhk[FHN * CSZ * FDIM];
__device__ __align__(16) float g_vl1[FHN * CSZ * FDIM];
__device__ __align__(16) float g_hqa[NCH * FHN * CSZ * FDIM];

// ------------------------- side stream + events -------------------------
struct StreamCtx {
    cudaStream_t s2 = 0;
    cudaEvent_t e0 = 0, e1 = 0, e2 = 0, e3 = 0;
    cudaEvent_t ec[NCH] = {0, 0, 0, 0};
    bool ok = false;
    StreamCtx() {
        bool good = (cudaStreamCreateWithFlags(&s2, cudaStreamNonBlocking) == cudaSuccess);
        good = good && (cudaEventCreateWithFlags(&e0, cudaEventDisableTiming) == cudaSuccess);
        good = good && (cudaEventCreateWithFlags(&e1, cudaEventDisableTiming) == cudaSuccess);
        good = good && (cudaEventCreateWithFlags(&e2, cudaEventDisableTiming) == cudaSuccess);
        good = good && (cudaEventCreateWithFlags(&e3, cudaEventDisableTiming) == cudaSuccess);
        for (int i = 0; i < NCH; i++)
            good = good && (cudaEventCreateWithFlags(&ec[i], cudaEventDisableTiming) == cudaSuccess);
        ok = good;
    }
};
static StreamCtx g_sc;

// ------------------------- tf32 mma primitives -------------------------
__device__ __forceinline__ unsigned f2tf(float f)
{
    unsigned u;
    asm("cvt.rna.tf32.f32 %0, %1;" : "=r"(u) : "f"(f));
    return u;
}

__device__ __forceinline__ void mma8(float* c, const unsigned* a, const unsigned* b)
{
    asm volatile(
        "mma.sync.aligned.m16n8k8.row.col.f32.tf32.tf32.f32 "
        "{%0,%1,%2,%3},{%4,%5,%6,%7},{%8,%9},{%0,%1,%2,%3};"
        : "+f"(c[0]), "+f"(c[1]), "+f"(c[2]), "+f"(c[3])
        : "r"(a[0]), "r"(a[1]), "r"(a[2]), "r"(a[3]), "r"(b[0]), "r"(b[1]));
}

#define SSTR 136

__device__ __forceinline__ void mma_block(
    const unsigned (*As)[SSTR], const unsigned (*Bs)[SSTR],
    float acc[4][4][4], int wm, int wn, int gid, int tig)
{
#pragma unroll
    for (int kh = 0; kh < 16; kh += 8) {
        unsigned a[4][4], b[4][2];
#pragma unroll
        for (int fm = 0; fm < 4; fm++) {
            int mb = wm * 64 + fm * 16;
            a[fm][0] = As[kh + tig][mb + gid];
            a[fm][1] = As[kh + tig][mb + gid + 8];
            a[fm][2] = As[kh + tig + 4][mb + gid];
            a[fm][3] = As[kh + tig + 4][mb + gid + 8];
        }
#pragma unroll
        for (int fn = 0; fn < 4; fn++) {
            int nb = wn * 32 + fn * 8;
            b[fn][0] = Bs[kh + tig][nb + gid];
            b[fn][1] = Bs[kh + tig + 4][nb + gid];
        }
#pragma unroll
        for (int fm = 0; fm < 4; fm++)
#pragma unroll
            for (int fn = 0; fn < 4; fn++) mma8(acc[fm][fn], a[fm], b[fn]);
    }
}

// ------------------------- generic tf32 GEMM (CTA 128x128) -------------------------
// mode: 0 store, 1 +=, 2 atomicAdd
__device__ __forceinline__ void gemm128(
    const float* __restrict__ A, const float* __restrict__ B, float* __restrict__ C,
    int m0, int n0, int K, int lda, int ldb, int ldc,
    bool transA, bool transB, int mode)
{
    __shared__ __align__(16) unsigned As[2][16][SSTR];
    __shared__ __align__(16) unsigned Bs[2][16][SSTR];
    const int tid = threadIdx.x;
    const int lane = tid & 31, warp = tid >> 5;
    const int wm = warp >> 2, wn = warp & 3;
    const int gid = lane >> 2, tig = lane & 3;

    float acc[4][4][4];
#pragma unroll
    for (int i = 0; i < 4; i++)
#pragma unroll
        for (int j = 0; j < 4; j++)
#pragma unroll
            for (int l = 0; l < 4; l++) acc[i][j][l] = 0.0f;

    float4 ar[2], br[2];
    auto fetchA = [&](int k0) {
#pragma unroll
        for (int s = 0; s < 2; s++) {
            int lin = tid + 256 * s;
            if (!transA) {
                int m = lin >> 2, kq = (lin & 3) * 4;
                ar[s] = *(const float4*)(A + (long)(m0 + m) * lda + (k0 + kq));
            } else {
                int k = lin >> 5, m4 = (lin & 31) * 4;
                ar[s] = *(const float4*)(A + (long)(k0 + k) * lda + (m0 + m4));
            }
        }
    };
    auto fetchB = [&](int k0) {
#pragma unroll
        for (int s = 0; s < 2; s++) {
            int lin = tid + 256 * s;
            if (transB) {
                int n = lin >> 2, kq = (lin & 3) * 4;
                br[s] = *(const float4*)(B + (long)(n0 + n) * ldb + (k0 + kq));
            } else {
                int k = lin >> 5, n4 = (lin & 31) * 4;
                br[s] = *(const float4*)(B + (long)(k0 + k) * ldb + (n0 + n4));
            }
        }
    };
    auto storeA = [&](int buf) {
#pragma unroll
        for (int s = 0; s < 2; s++) {
            int lin = tid + 256 * s;
            if (!transA) {
                int m = lin >> 2, kq = (lin & 3) * 4;
                As[buf][kq + 0][m] = f2tf(ar[s].x);
                As[buf][kq + 1][m] = f2tf(ar[s].y);
                As[buf][kq + 2][m] = f2tf(ar[s].z);
                As[buf][kq + 3][m] = f2tf(ar[s].w);
            } else {
                int k = lin >> 5, m4 = (lin & 31) * 4;
                uint4 u = {f2tf(ar[s].x), f2tf(ar[s].y), f2tf(ar[s].z), f2tf(ar[s].w)};
                *(uint4*)&As[buf][k][m4] = u;
            }
        }
    };
    auto storeB = [&](int buf) {
#pragma unroll
        for (int s = 0; s < 2; s++) {
            int lin = tid + 256 * s;
            if (transB) {
                int n = lin >> 2, kq = (lin & 3) * 4;
                Bs[buf][kq + 0][n] = f2tf(br[s].x);
                Bs[buf][kq + 1][n] = f2tf(br[s].y);
                Bs[buf][kq + 2][n] = f2tf(br[s].z);
                Bs[buf][kq + 3][n] = f2tf(br[s].w);
            } else {
                int k = lin >> 5, n4 = (lin & 31) * 4;
                uint4 u = {f2tf(br[s].x), f2tf(br[s].y), f2tf(br[s].z), f2tf(br[s].w)};
                *(uint4*)&Bs[buf][k][n4] = u;
            }
        }
    };

    const int nk = K >> 4;
    fetchA(0); fetchB(0); storeA(0); storeB(0);
    __syncthreads();
    for (int t = 0; t < nk; t++) {
        const int cur = t & 1;
        if (t + 1 < nk) { fetchA((t + 1) << 4); fetchB((t + 1) << 4); }
        mma_block(As[cur], Bs[cur], acc, wm, wn, gid, tig);
        if (t + 1 < nk) { storeA(cur ^ 1); storeB(cur ^ 1); }
        __syncthreads();
    }

#pragma unroll
    for (int fm = 0; fm < 4; fm++) {
        int r0 = m0 + wm * 64 + fm * 16 + gid;
#pragma unroll
        for (int fn = 0; fn < 4; fn++) {
            int cc = n0 + wn * 32 + fn * 8 + 2 * tig;
            float* p0 = C + (long)r0 * ldc + cc;
            float* p1 = C + (long)(r0 + 8) * ldc + cc;
            if (mode == 0) {
                p0[0] = acc[fm][fn][0]; p0[1] = acc[fm][fn][1];
                p1[0] = acc[fm][fn][2]; p1[1] = acc[fm][fn][3];
            } else if (mode == 1) {
                p0[0] += acc[fm][fn][0]; p0[1] += acc[fm][fn][1];
                p1[0] += acc[fm][fn][2]; p1[1] += acc[fm][fn][3];
            } else {
                atomicAdd(p0, acc[fm][fn][0]); atomicAdd(p0 + 1, acc[fm][fn][1]);
                atomicAdd(p1, acc[fm][fn][2]); atomicAdd(p1 + 1, acc[fm][fn][3]);
            }
        }
    }
}

// ------------------------- helpers -------------------------
__device__ __forceinline__ float sigmoidf_(float x) { return 1.0f / (1.0f + expf(-x)); }
__device__ __forceinline__ float warp_sum(float v)
{
#pragma unroll
    for (int o = 16; o > 0; o >>= 1) v += __shfl_xor_sync(0xffffffffu, v, o);
    return v;
}

// ------------------------- kernels -------------------------
__global__ void k_initW(const float* __restrict__ w0, const float* __restrict__ w1,
                        const float* __restrict__ w2)
{
    int i = blockIdx.x * blockDim.x + threadIdx.x;
    if (i < FHN * FDIM * FDIM) { g_W0[i] = w0[i]; g_W1[i] = w1[i]; g_W2[i] = w2[i]; }
}

__global__ __launch_bounds__(256) void k_gemm_qkv(const float* __restrict__ x,
                                                  const float* __restrict__ Wqkv)
{
    gemm128(x, Wqkv, g_qkv, blockIdx.y * 128, blockIdx.x * 128,
            DIM, DIM, DIM, 3 * DIM, false, true, 0);
}

__global__ __launch_bounds__(128) void k_lr(const float* __restrict__ x,
                                            const float* __restrict__ Wlr,
                                            const float* __restrict__ blr)
{
    __shared__ __align__(16) float sx[DIM];
    int s = blockIdx.x;
    for (int i = threadIdx.x; i < DIM; i += 128) sx[i] = x[(long)s * DIM + i];
    __syncthreads();
    int w = threadIdx.x >> 5, lane = threadIdx.x & 31;
    for (int j = w; j < 12; j += 4) {
        float sum = 0.0f;
        for (int d = lane; d < DIM; d += 32) sum += sx[d] * Wlr[(long)j * DIM + d];
        sum = warp_sum(sum);
        if (lane == 0) {
            float v = sum + blr[j] + BASE_LR_INV;
            g_lrbuf[s * 12 + j] = (v > 20.0f) ? v : log1pf(expf(v));
        }
    }
}

// RMSNorm(q,k) + fw inputs + fv + RoPE — float4 vectorized
__global__ __launch_bounds__(256) void k_post(const float* __restrict__ qnw,
                                              const float* __restrict__ knw,
                                              const float* __restrict__ qks,
                                              const float* __restrict__ qko)
{
    __shared__ __align__(16) float s_q[DIM];
    __shared__ __align__(16) float s_k[DIM];
    __shared__ __align__(16) float s_cs[32];
    __shared__ __align__(16) float s_sn[32];
    __shared__ float s_w2[8][2];
    __shared__ float s_hq[8], s_hk[8];
    __shared__ float s_fin[2];

    int s = blockIdx.x, t = threadIdx.x, lane = t & 31, w = t >> 5;
    const float* qrow = g_qkv + (long)s * 3072;

    if (t < 32) {
        double inv = exp(-((double)(2 * t) / 64.0) * log(500000.0));
        double a = (double)s * inv;
        const double tw = 6.283185307179586476925286766559;
        a -= floor(a / tw) * tw;
        s_cs[t] = (float)cos(a);
        s_sn[t] = (float)sin(a);
    }

    int d = 4 * t;
    float4 q4 = *(const float4*)(qrow + d);
    float4 k4 = *(const float4*)(qrow + DIM + d);
    float4 v4 = *(const float4*)(qrow + 2 * DIM + d);

    float sq = q4.x * q4.x + q4.y * q4.y + q4.z * q4.z + q4.w * q4.w;
    float sk = k4.x * k4.x + k4.y * k4.y + k4.z * k4.z + k4.w * k4.w;
    sq = warp_sum(sq); sk = warp_sum(sk);
    if (lane == 0) { s_w2[w][0] = sq; s_w2[w][1] = sk; }
    __syncthreads();
    if (t < 2) {
        float a = 0.0f;
#pragma unroll
        for (int i = 0; i < 8; i++) a += s_w2[i][t];
        s_fin[t] = a;
    }
    __syncthreads();
    float rq = rsqrtf(s_fin[0] / 1024.0f + 1e-5f);
    float rk = rsqrtf(s_fin[1] / 1024.0f + 1e-5f);

    float4 qw4 = *(const float4*)(qnw + d);
    float4 kw4 = *(const float4*)(knw + d);
    float qn[4] = {q4.x * rq * qw4.x, q4.y * rq * qw4.y, q4.z * rq * qw4.z, q4.w * rq * qw4.w};
    float kn[4] = {k4.x * rk * kw4.x, k4.y * rk * kw4.y, k4.z * rk * kw4.z, k4.w * rk * kw4.w};
    *(float4*)&s_q[d] = make_float4(qn[0], qn[1], qn[2], qn[3]);
    *(float4*)&s_k[d] = make_float4(kn[0], kn[1], kn[2], kn[3]);

    float4 qsA = *(const float4*)(qks + 2 * d);
    float4 qsB = *(const float4*)(qks + 2 * d + 4);
    float4 qoA = *(const float4*)(qko + 2 * d);
    float4 qoB = *(const float4*)(qko + 2 * d + 4);
    float scq[4] = {qsA.x, qsA.z, qsB.x, qsB.z};
    float sck[4] = {qsA.y, qsA.w, qsB.y, qsB.w};
    float ofq[4] = {qoA.x, qoA.z, qoB.x, qoB.z};
    float ofk[4] = {qoA.y, qoA.w, qoB.y, qoB.w};

    float fq[4], fk[4], fv[4];
    float sqq = 0.0f, skk = 0.0f;
    float vvv[4] = {v4.x, v4.y, v4.z, v4.w};
#pragma unroll
    for (int j = 0; j < 4; j++) {
        fq[j] = qn[j] * sigmoidf_(qn[j]) * scq[j] + ofq[j];
        fk[j] = kn[j] * sigmoidf_(kn[j]) * sck[j] + ofk[j];
        fv[j] = vvv[j] * sigmoidf_(vvv[j]);
        sqq += fq[j] * fq[j];
        skk += fk[j] * fk[j];
    }
    *(float4*)&g_fv[(long)s * DIM + d] = make_float4(fv[0], fv[1], fv[2], fv[3]);

    sqq = warp_sum(sqq); skk = warp_sum(skk);
    if (lane == 0) { s_hq[w] = sqq; s_hk[w] = skk; }
    __syncthreads();
    float rfq = rsqrtf(s_hq[w & ~1] + s_hq[w | 1] + 1e-6f);
    float rfk = rsqrtf(s_hk[w & ~1] + s_hk[w | 1] + 1e-6f);
#pragma unroll
    for (int j = 0; j < 4; j++) { fq[j] *= rfq; fk[j] *= rfk; }
    *(float4*)&g_fq[(long)s * DIM + d] = make_float4(fq[0], fq[1], fq[2], fq[3]);
    *(float4*)&g_fk[(long)s * DIM + d] = make_float4(fk[0], fk[1], fk[2], fk[3]);

    int r = d & 63, ip = d & 31;
    float4 cs = *(float4*)&s_cs[ip];
    float4 sn = *(float4*)&s_sn[ip];
    float4 xq = *(float4*)&s_q[d], xpq = *(float4*)&s_q[d ^ 32];
    float4 xk = *(float4*)&s_k[d], xpk = *(float4*)&s_k[d ^ 32];
    float sgn = (r < 32) ? -1.0f : 1.0f;
    *(float4*)&g_qr[(long)s * DIM + d] = make_float4(
        xq.x * cs.x + sgn * xpq.x * sn.x, xq.y * cs.y + sgn * xpq.y * sn.y,
        xq.z * cs.z + sgn * xpq.z * sn.z, xq.w * cs.w + sgn * xpq.w * sn.w);
    *(float4*)&g_kr[(long)s * DIM + d] = make_float4(
        xk.x * cs.x + sgn * xpk.x * sn.x, xk.y * cs.y + sgn * xpk.y * sn.y,
        xk.z * cs.z + sgn * xpk.z * sn.z, xk.w * cs.w + sgn * xpk.w * sn.w);
}

// TTT stage 1: gk,hk,qg,qm,dh GEMMs + W1 snapshot (z = h*6+op)
__global__ __launch_bounds__(256) void k_ttt1(int c)
{
    int z = blockIdx.z;
    int h = z / 6, op = z - h * 6;
    if (op == 5) {
        int cta = blockIdx.y * 2 + blockIdx.x;
        const float4* src = (const float4*)(g_W1 + h * FDIM * FDIM);
        float4* dst = (float4*)(g_W1c + ((long)c * FHN + h) * FDIM * FDIM);
#pragma unroll
        for (int j = 0; j < 4; j++) {
            int idx = j * 4096 + cta * 256 + threadIdx.x;
            dst[idx] = src[idx];
        }
        return;
    }
    long choff = (long)c * CSZ * DIM + h * FDIM;
    const float* A; const float* B; float* Cp; bool tb = true;
    switch (op) {
        case 0: A = g_fk + choff; B = g_W0 + h * FDIM * FDIM; Cp = g_gk + (long)h * CSZ * FDIM; break;
        case 1: A = g_fk + choff; B = g_W2 + h * FDIM * FDIM; Cp = g_hk + (long)h * CSZ * FDIM; break;
        case 2: A = g_fq + choff; B = g_W0 + h * FDIM * FDIM; Cp = g_qg + (long)h * CSZ * FDIM; break;
        case 3: A = g_fq + choff; B = g_W2 + h * FDIM * FDIM; Cp = g_qm + (long)h * CSZ * FDIM; break;
        default: A = g_fv + choff; B = g_W1 + h * FDIM * FDIM;
                Cp = g_dh + (long)h * CSZ * FDIM; tb = false; break;
    }
    gemm128(A, B, Cp, blockIdx.y * 128, blockIdx.x * 128, FDIM, DIM, FDIM, FDIM, false, tb, 0);
}

// TTT stage 2: elementwise activations / lr scaling — float4 vectorized
__global__ __launch_bounds__(256) void k_ttt2(int c)
{
    long idx = ((long)blockIdx.x * 256 + threadIdx.x) * 4;
    int h = (int)(idx >> 18);
    int rem = (int)(idx & 262143);
    int t = rem >> 8;
    int e = rem & 255;
    int sg = c * CSZ + t;
    float l0 = g_lrbuf[sg * 12 + h];
    float l1 = g_lrbuf[sg * 12 + 4 + h];
    float l2 = g_lrbuf[sg * 12 + 8 + h];
    float4 gk4 = *(const float4*)&g_gk[idx];
    float4 hk4 = *(const float4*)&g_hk[idx];
    float4 dh4 = *(const float4*)&g_dh[idx];
    float4 qg4 = *(const float4*)&g_qg[idx];
    float4 qm4 = *(const float4*)&g_qm[idx];
    float4 fv4 = *(const float4*)&g_fv[(long)sg * DIM + h * FDIM + e];
    float gk[4] = {gk4.x, gk4.y, gk4.z, gk4.w};
    float hk[4] = {hk4.x, hk4.y, hk4.z, hk4.w};
    float dh[4] = {dh4.x, dh4.y, dh4.z, dh4.w};
    float qg[4] = {qg4.x, qg4.y, qg4.z, qg4.w};
    float qm[4] = {qm4.x, qm4.y, qm4.z, qm4.w};
    float fv[4] = {fv4.x, fv4.y, fv4.z, fv4.w};
    float hq[4], hid[4], dgk[4], dhk[4], vl1[4];
#pragma unroll
    for (int j = 0; j < 4; j++) {
        float sgm = sigmoidf_(gk[j]);
        float sil = gk[j] * sgm;
        hq[j] = qg[j] * sigmoidf_(qg[j]) * qm[j];
        hid[j] = sil * hk[j];
        float dsil = sgm * (1.0f + gk[j] * (1.0f - sgm));
        dgk[j] = dh[j] * hk[j] * dsil * l0;
        dhk[j] = dh[j] * sil * l2;
        vl1[j] = fv[j] * l1;
    }
    *(float4*)&g_hqa[(long)c * FHN * CSZ * FDIM + idx] = make_float4(hq[0], hq[1], hq[2], hq[3]);
    *(float4*)&g_hid[idx] = make_float4(hid[0], hid[1], hid[2], hid[3]);
    *(float4*)&g_dgk[idx] = make_float4(dgk[0], dgk[1], dgk[2], dgk[3]);
    *(float4*)&g_dhk[idx] = make_float4(dhk[0], dhk[1], dhk[2], dhk[3]);
    *(float4*)&g_vl1[idx] = make_float4(vl1[0], vl1[1], vl1[2], vl1[3]);
}

// TTT stage 4: rank-CSZ weight updates, split-K 8x with atomic accumulate
__global__ __launch_bounds__(256) void k_ttt4(int c)
{
    int z = blockIdx.z;
    int h = z / 24;
    int r = z - h * 24;
    int op = r >> 3, sl = r & 7;
    long koff = (long)c * CSZ * DIM + h * FDIM;
    const float* A; const float* B; float* Cp; int lda, ldb;
    switch (op) {
        case 0: A = g_vl1 + (long)h * CSZ * FDIM; B = g_hid + (long)h * CSZ * FDIM;
                Cp = g_W1 + h * FDIM * FDIM; lda = FDIM; ldb = FDIM; break;
        case 1: A = g_dgk + (long)h * CSZ * FDIM; B = g_fk + koff;
                Cp = g_W0 + h * FDIM * FDIM; lda = FDIM; ldb = DIM; break;
        default: A = g_dhk + (long)h * CSZ * FDIM; B = g_fk + koff;
                Cp = g_W2 + h * FDIM * FDIM; lda = FDIM; ldb = DIM; break;
    }
    A += (long)sl * 128 * lda;
    B += (long)sl * 128 * ldb;
    gemm128(A, B, Cp, blockIdx.y * 128, blockIdx.x * 128, 128, lda, ldb, FDIM, true, false, 2);
}

// Deferred TTT stage 3, one chunk (runs on side stream in loop shadow)
__global__ __launch_bounds__(256) void k_ttt3c(int c)
{
    int h = blockIdx.z;
    gemm128(g_hqa + ((long)c * FHN + h) * CSZ * FDIM,
            g_W1c + ((long)c * FHN + h) * FDIM * FDIM,
            g_ttt + (long)c * CSZ * DIM + h * FDIM,
            blockIdx.y * 128, blockIdx.x * 128, FDIM, FDIM, FDIM, DIM, false, true, 0);
}

// ------------------------- tf32 flash attention -------------------------
#define SQSTR 68
#define SKSTR 68
#define SVSTR 72
#define ATTN_SMEM ((128 * SQSTR + 64 * SKSTR + 64 * SVSTR) * 4)

__global__ __launch_bounds__(256) void k_attn()
{
    extern __shared__ __align__(16) float sm[];
    float* sQP = sm;
    unsigned* sK = (unsigned*)(sm + 128 * SQSTR);
    unsigned* sV = (unsigned*)(sm + 128 * SQSTR + 64 * SKSTR);

    const int h = blockIdx.y, qt = blockIdx.x;
    const int p0 = qt * 128;
    const int tid = threadIdx.x;
    const int lane = tid & 31, warp = tid >> 5;
    const int gid = lane >> 2, tig = lane & 3;

#pragma unroll
    for (int s = 0; s < 8; s++) {
        int lin = tid + 256 * s;
        int r = lin >> 4, c4 = (lin & 15) * 4;
        *(float4*)&sQP[r * SQSTR + c4] =
            *(const float4*)&g_qr[(long)(p0 + r) * DIM + h * HDIM + c4];
    }
    __syncthreads();

    const int rq = warp * 16 + gid;
    unsigned qa[8][4];
#pragma unroll
    for (int kb = 0; kb < 8; kb++) {
        qa[kb][0] = f2tf(0.125f * sQP[rq * SQSTR + kb * 8 + tig]);
        qa[kb][1] = f2tf(0.125f * sQP[(rq + 8) * SQSTR + kb * 8 + tig]);
        qa[kb][2] = f2tf(0.125f * sQP[rq * SQSTR + kb * 8 + tig + 4]);
        qa[kb][3] = f2tf(0.125f * sQP[(rq + 8) * SQSTR + kb * 8 + tig + 4]);
    }

    float o[8][4];
#pragma unroll
    for (int fn = 0; fn < 8; fn++)
#pragma unroll
        for (int j = 0; j < 4; j++) o[fn][j] = 0.0f;
    float mrow0 = -1e30f, mrow1 = -1e30f, lsum0 = 0.0f, lsum1 = 0.0f;

    const int ktlo = (qt >= 8) ? 2 * qt - 16 : 0;
    const int kthi = 2 * qt + 1;
    const int prow0 = p0 + warp * 16 + gid;
    const int prow1 = prow0 + 8;

    for (int kt = ktlo; kt <= kthi; kt++) {
        __syncthreads();
#pragma unroll
        for (int s = 0; s < 4; s++) {
            int lin = tid + 256 * s;
            int r = lin >> 4, c4 = (lin & 15) * 4;
            float4 kv = *(const float4*)&g_kr[(long)(kt * 64 + r) * DIM + h * HDIM + c4];
            uint4 ku = {f2tf(kv.x), f2tf(kv.y), f2tf(kv.z), f2tf(kv.w)};
            *(uint4*)&sK[r * SKSTR + c4] = ku;
            float4 vv = *(const float4*)&g_qkv[(long)(kt * 64 + r) * 3072 + 2048 + h * HDIM + c4];
            uint4 vu = {f2tf(vv.x), f2tf(vv.y), f2tf(vv.z), f2tf(vv.w)};
            *(uint4*)&sV[r * SVSTR + c4] = vu;
        }
        __syncthreads();

        float sc[8][4];
#pragma unroll
        for (int fn = 0; fn < 8; fn++)
#pragma unroll
            for (int j = 0; j < 4; j++) sc[fn][j] = 0.0f;
#pragma unroll
        for (int kb = 0; kb < 8; kb++) {
#pragma unroll
            for (int fn = 0; fn < 8; fn++) {
                unsigned b[2];
                b[0] = sK[(fn * 8 + gid) * SKSTR + kb * 8 + tig];
                b[1] = sK[(fn * 8 + gid) * SKSTR + kb * 8 + tig + 4];
                mma8(sc[fn], qa[kb], b);
            }
        }
#pragma unroll
        for (int fn = 0; fn < 8; fn++) {
            int g0 = kt * 64 + fn * 8 + 2 * tig;
            int g1 = g0 + 1;
            sc[fn][0] = (g0 > prow0 - 1024 && g0 <= prow0) ? sc[fn][0] : -1e30f;
            sc[fn][1] = (g1 > prow0 - 1024 && g1 <= prow0) ? sc[fn][1] : -1e30f;
            sc[fn][2] = (g0 > prow1 - 1024 && g0 <= prow1) ? sc[fn][2] : -1e30f;
            sc[fn][3] = (g1 > prow1 - 1024 && g1 <= prow1) ? sc[fn][3] : -1e30f;
        }
        float t0 = -1e30f, t1 = -1e30f;
#pragma unroll
        for (int fn = 0; fn < 8; fn++) {
            t0 = fmaxf(t0, fmaxf(sc[fn][0], sc[fn][1]));
            t1 = fmaxf(t1, fmaxf(sc[fn][2], sc[fn][3]));
        }
#pragma unroll
        for (int off = 1; off < 4; off <<= 1) {
            t0 = fmaxf(t0, __shfl_xor_sync(0xffffffffu, t0, off));
            t1 = fmaxf(t1, __shfl_xor_sync(0xffffffffu, t1, off));
        }
        float mn0 = fmaxf(mrow0, t0), mn1 = fmaxf(mrow1, t1);
        float al0 = expf(mrow0 - mn0), al1 = expf(mrow1 - mn1);
        float mc0 = fmaxf(mn0, -1e20f), mc1 = fmaxf(mn1, -1e20f);
        float rs0 = 0.0f, rs1 = 0.0f;
#pragma unroll
        for (int fn = 0; fn < 8; fn++) {
            sc[fn][0] = expf(sc[fn][0] - mc0);
            sc[fn][1] = expf(sc[fn][1] - mc0);
            sc[fn][2] = expf(sc[fn][2] - mc1);
            sc[fn][3] = expf(sc[fn][3] - mc1);
            rs0 += sc[fn][0] + sc[fn][1];
            rs1 += sc[fn][2] + sc[fn][3];
        }
#pragma unroll
        for (int off = 1; off < 4; off <<= 1) {
            rs0 += __shfl_xor_sync(0xffffffffu, rs0, off);
            rs1 += __shfl_xor_sync(0xffffffffu, rs1, off);
        }
        lsum0 = lsum0 * al0 + rs0;
        lsum1 = lsum1 * al1 + rs1;
        mrow0 = mn0; mrow1 = mn1;
#pragma unroll
        for (int fn = 0; fn < 8; fn++) {
            o[fn][0] *= al0; o[fn][1] *= al0;
            o[fn][2] *= al1; o[fn][3] *= al1;
        }
        const int rp = warp * 16 + gid;
#pragma unroll
        for (int fn = 0; fn < 8; fn++) {
            sQP[rp * SQSTR + fn * 8 + 2 * tig]           = sc[fn][0];
            sQP[rp * SQSTR + fn * 8 + 2 * tig + 1]       = sc[fn][1];
            sQP[(rp + 8) * SQSTR + fn * 8 + 2 * tig]     = sc[fn][2];
            sQP[(rp + 8) * SQSTR + fn * 8 + 2 * tig + 1] = sc[fn][3];
        }
        __syncwarp();
#pragma unroll
        for (int kb = 0; kb < 8; kb++) {
            unsigned pa[4];
            pa[0] = f2tf(sQP[rp * SQSTR + kb * 8 + tig]);
            pa[1] = f2tf(sQP[(rp + 8) * SQSTR + kb * 8 + tig]);
            pa[2] = f2tf(sQP[rp * SQSTR + kb * 8 + tig + 4]);
            pa[3] = f2tf(sQP[(rp + 8) * SQSTR + kb * 8 + tig + 4]);
#pragma unroll
            for (int fn = 0; fn < 8; fn++) {
                unsigned b[2];
                b[0] = sV[(kb * 8 + tig) * SVSTR + fn * 8 + gid];
                b[1] = sV[(kb * 8 + tig + 4) * SVSTR + fn * 8 + gid];
                mma8(o[fn], pa, b);
            }
        }
        __syncwarp();
    }

    float inv0 = 1.0f / lsum0, inv1 = 1.0f / lsum1;
#pragma unroll
    for (int fn = 0; fn < 8; fn++) {
        int cc = h * HDIM + fn * 8 + 2 * tig;
        g_ao[(long)prow0 * DIM + cc]     = o[fn][0] * inv0;
        g_ao[(long)prow0 * DIM + cc + 1] = o[fn][1] * inv0;
        g_ao[(long)prow1 * DIM + cc]     = o[fn][2] * inv1;
        g_ao[(long)prow1 * DIM + cc + 1] = o[fn][3] * inv1;
    }
}

// Per-(row, fw-head) rms factors of g_ttt (for fused output GEMM staging)
__global__ __launch_bounds__(256) void k_rms()
{
    __shared__ float s_h[8];
    int s = blockIdx.x, t = threadIdx.x, lane = t & 31, w = t >> 5;
    int d = 4 * t;
    float4 v4 = *(const float4*)&g_ttt[(long)s * DIM + d];
    float p = v4.x * v4.x + v4.y * v4.y + v4.z * v4.z + v4.w * v4.w;
    p = warp_sum(p);
    if (lane == 0) s_h[w] = p;
    __syncthreads();
    if (t < 4) {
        float tot = s_h[2 * t] + s_h[2 * t + 1];
        g_rms[s * FHN + t] = rsqrtf(tot / 256.0f + 1e-5f);
    }
}

// Output GEMM with fused (ao + rms(ttt)*tnw) A-staging: out = fused @ Wo^T
__global__ __launch_bounds__(256) void k_gemm_outf(const float* __restrict__ Wo,
                                                   const float* __restrict__ tnw,
                                                   float* __restrict__ out)
{
    __shared__ __align__(16) unsigned As[2][16][SSTR];
    __shared__ __align__(16) unsigned Bs[2][16][SSTR];
    const int m0 = blockIdx.y * 128, n0 = blockIdx.x * 128;
    const int tid = threadIdx.x;
    const int lane = tid & 31, warp = tid >> 5;
    const int wm = warp >> 2, wn = warp & 3;
    const int gid = lane >> 2, tig = lane & 3;

    float acc[4][4][4];
#pragma unroll
    for (int i = 0; i < 4; i++)
#pragma unroll
        for (int j = 0; j < 4; j++)
#pragma unroll
            for (int l = 0; l < 4; l++) acc[i][j][l] = 0.0f;

    float4 ao[2], tt[2], wn4[2], br[2];
    float rr[2];
    auto fetch = [&](int k0) {
#pragma unroll
        for (int s = 0; s < 2; s++) {
            int lin = tid + 256 * s;
            int m = lin >> 2, kq = (lin & 3) * 4;
            int k = k0 + kq;
            long off = (long)(m0 + m) * DIM + k;
            ao[s] = *(const float4*)&g_ao[off];
            tt[s] = *(const float4*)&g_ttt[off];
            rr[s] = g_rms[(m0 + m) * FHN + (k >> 8)];
            wn4[s] = *(const float4*)&tnw[k & 255];
            // B: Wo [N,K] row-major, transB
            int n = lin >> 2;
            br[s] = *(const float4*)(Wo + (long)(n0 + n) * DIM + k0 + kq);
        }
    };
    auto store = [&](int buf) {
#pragma unroll
        for (int s = 0; s < 2; s++) {
            int lin = tid + 256 * s;
            int m = lin >> 2, kq = (lin & 3) * 4;
            float a[4] = {ao[s].x + tt[s].x * rr[s] * wn4[s].x,
                          ao[s].y + tt[s].y * rr[s] * wn4[s].y,
                          ao[s].z + tt[s].z * rr[s] * wn4[s].z,
                          ao[s].w + tt[s].w * rr[s] * wn4[s].w};
            As[buf][kq + 0][m] = f2tf(a[0]);
            As[buf][kq + 1][m] = f2tf(a[1]);
            As[buf][kq + 2][m] = f2tf(a[2]);
            As[buf][kq + 3][m] = f2tf(a[3]);
            int n = lin >> 2;
            Bs[buf][kq + 0][n] = f2tf(br[s].x);
            Bs[buf][kq + 1][n] = f2tf(br[s].y);
            Bs[buf][kq + 2][n] = f2tf(br[s].z);
            Bs[buf][kq + 3][n] = f2tf(br[s].w);
        }
    };

    fetch(0); store(0);
    __syncthreads();
    for (int t = 0; t < 64; t++) {
        const int cur = t & 1;
        if (t + 1 < 64) fetch((t + 1) << 4);
        mma_block(As[cur], Bs[cur], acc, wm, wn, gid, tig);
        if (t + 1 < 64) store(cur ^ 1);
        __syncthreads();
    }

#pragma unroll
    for (int fm = 0; fm < 4; fm++) {
        int r0 = m0 + wm * 64 + fm * 16 + gid;
#pragma unroll
        for (int fn = 0; fn < 4; fn++) {
            int cc = n0 + wn * 32 + fn * 8 + 2 * tig;
            out[(long)r0 * DIM + cc] = acc[fm][fn][0];
            out[(long)r0 * DIM + cc + 1] = acc[fm][fn][1];
            out[(long)(r0 + 8) * DIM + cc] = acc[fm][fn][2];
            out[(long)(r0 + 8) * DIM + cc + 1] = acc[fm][fn][3];
        }
    }
}

// ------------------------- launch -------------------------
extern "C" void kernel_launch(void* const* d_in, const int* in_sizes, int n_in,
                              void* d_out, int out_size)
{
    const float* x    = (const float*)d_in[0];
    const float* Wqkv = (const float*)d_in[1];
    const float* qnw  = (const float*)d_in[2];
    const float* knw  = (const float*)d_in[3];
    const float* Wo   = (const float*)d_in[4];
    const float* w0   = (const float*)d_in[5];
    const float* w1   = (const float*)d_in[6];
    const float* w2   = (const float*)d_in[7];
    const float* Wlr  = (const float*)d_in[8];
    const float* blr  = (const float*)d_in[9];
    const float* qks  = (const float*)d_in[10];
    const float* qko  = (const float*)d_in[11];
    const float* tnw  = (const float*)d_in[12];
    float* out = (float*)d_out;

    cudaFuncSetAttribute(k_attn, cudaFuncAttributeMaxDynamicSharedMemorySize, ATTN_SMEM);

    cudaStream_t s2 = g_sc.s2;

    if (g_sc.ok) {
        cudaEventRecord(g_sc.e0, 0);
        cudaStreamWaitEvent(s2, g_sc.e0, 0);
        k_initW<<<1024, 256, 0, s2>>>(w0, w1, w2);
        k_lr<<<4096, 128, 0, s2>>>(x, Wlr, blr);
        cudaEventRecord(g_sc.e1, s2);

        k_gemm_qkv<<<dim3(24, 32), 256>>>(x, Wqkv);
        k_post<<<4096, 256>>>(qnw, knw, qks, qko);

        cudaEventRecord(g_sc.e2, 0);
        cudaStreamWaitEvent(s2, g_sc.e2, 0);
        k_attn<<<dim3(32, NHEAD), 256, ATTN_SMEM, s2>>>();

        cudaStreamWaitEvent(0, g_sc.e1, 0);
        for (int c = 0; c < NCH; c++) {
            k_ttt1<<<dim3(2, 8, 24), 256>>>(c);
            k_ttt2<<<1024, 256>>>(c);
            cudaEventRecord(g_sc.ec[c], 0);
            cudaStreamWaitEvent(s2, g_sc.ec[c], 0);
            k_ttt3c<<<dim3(2, 8, 4), 256, 0, s2>>>(c);
            k_ttt4<<<dim3(2, 2, 96), 256>>>(c);
        }
        cudaEventRecord(g_sc.e3, s2);

        cudaStreamWaitEvent(0, g_sc.e3, 0);
        k_rms<<<4096, 256>>>();
        k_gemm_outf<<<dim3(8, 32), 256>>>(Wo, tnw, out);
    } else {
        k_initW<<<1024, 256>>>(w0, w1, w2);
        k_gemm_qkv<<<dim3(24, 32), 256>>>(x, Wqkv);
        k_lr<<<4096, 128>>>(x, Wlr, blr);
        k_post<<<4096, 256>>>(qnw, knw, qks, qko);
        for (int c = 0; c < NCH; c++) {
            k_ttt1<<<dim3(2, 8, 24), 256>>>(c);
            k_ttt2<<<1024, 256>>>(c);
            k_ttt3c<<<dim3(2, 8, 4), 256>>>(c);
            k_ttt4<<<dim3(2, 2, 96), 256>>>(c);
        }
        k_attn<<<dim3(32, NHEAD), 256, ATTN_SMEM>>>();
        k_rms<<<4096, 256>>>();
        k_gemm_outf<<<dim3(8, 32), 256>>>(Wo, tnw, out);
    }
}

// round 13
// speedup vs baseline: 1.0358x; 1.0321x over previous
#include <cuda_runtime.h>
#include <math.h>

#define SEQ   4096
#define DIM   1024
#define NHEAD 16
#define HDIM  64
#define FHN   4
#define FDIM  256
#define CSZ   1024
#define NCH   4
#define BASE_LR_INV -6.90725517f

// ------------------------- scratch (static device globals, 16B aligned) ------------
__device__ __align__(16) float g_qkv[SEQ * 3 * DIM];
__device__ __align__(16) float g_qr[SEQ * DIM];
__device__ __align__(16) float g_kr[SEQ * DIM];
__device__ __align__(16) float g_fq[SEQ * DIM];
__device__ __align__(16) float g_fk[SEQ * DIM];
__device__ __align__(16) float g_fv[SEQ * DIM];
__device__ __align__(16) float g_lrbuf[SEQ * 12];
__device__ __align__(16) float g_ttt[SEQ * DIM];
__device__ __align__(16) float g_ao[SEQ * DIM];
__device__ __align__(16) float g_W0[FHN * FDIM * FDIM];
__device__ __align__(16) float g_W1[FHN * FDIM * FDIM];
__device__ __align__(16) float g_W2[FHN * FDIM * FDIM];
__device__ __align__(16) float g_W1c[NCH * FHN * FDIM * FDIM];
__device__ __align__(16) float g_gk[FHN * CSZ * FDIM];
__device__ __align__(16) float g_hk[FHN * CSZ * FDIM];
__device__ __align__(16) float g_qg[FHN * CSZ * FDIM];
__device__ __align__(16) float g_qm[FHN * CSZ * FDIM];
__device__ __align__(16) float g_dh[FHN * CSZ * FDIM];
__device__ __align__(16) float g_hid[FHN * CSZ * FDIM];
__device__ __align__(16) float g_dgk[FHN * CSZ * FDIM];
__device__ __align__(16) float g_dhk[FHN * CSZ * FDIM];
__device__ __align__(16) float g_vl1[FHN * CSZ * FDIM];
__device__ __align__(16) float g_hqa[NCH * FHN * CSZ * FDIM];

// ------------------------- side stream + events -------------------------
struct StreamCtx {
    cudaStream_t s2 = 0;
    cudaEvent_t e0 = 0, e1 = 0, e2 = 0, e3 = 0;
    cudaEvent_t ec[NCH] = {0, 0, 0, 0};
    bool ok = false;
    StreamCtx() {
        bool good = (cudaStreamCreateWithFlags(&s2, cudaStreamNonBlocking) == cudaSuccess);
        good = good && (cudaEventCreateWithFlags(&e0, cudaEventDisableTiming) == cudaSuccess);
        good = good && (cudaEventCreateWithFlags(&e1, cudaEventDisableTiming) == cudaSuccess);
        good = good && (cudaEventCreateWithFlags(&e2, cudaEventDisableTiming) == cudaSuccess);
        good = good && (cudaEventCreateWithFlags(&e3, cudaEventDisableTiming) == cudaSuccess);
        for (int i = 0; i < NCH; i++)
            good = good && (cudaEventCreateWithFlags(&ec[i], cudaEventDisableTiming) == cudaSuccess);
        ok = good;
    }
};
static StreamCtx g_sc;

// ------------------------- tf32 mma primitives -------------------------
__device__ __forceinline__ unsigned f2tf(float f)
{
    unsigned u;
    asm("cvt.rna.tf32.f32 %0, %1;" : "=r"(u) : "f"(f));
    return u;
}

__device__ __forceinline__ void mma8(float* c, const unsigned* a, const unsigned* b)
{
    asm volatile(
        "mma.sync.aligned.m16n8k8.row.col.f32.tf32.tf32.f32 "
        "{%0,%1,%2,%3},{%4,%5,%6,%7},{%8,%9},{%0,%1,%2,%3};"
        : "+f"(c[0]), "+f"(c[1]), "+f"(c[2]), "+f"(c[3])
        : "r"(a[0]), "r"(a[1]), "r"(a[2]), "r"(a[3]), "r"(b[0]), "r"(b[1]));
}

#define SSTR 136

__device__ __forceinline__ void mma_block(
    const unsigned (*As)[SSTR], const unsigned (*Bs)[SSTR],
    float acc[4][4][4], int wm, int wn, int gid, int tig)
{
#pragma unroll
    for (int kh = 0; kh < 16; kh += 8) {
        unsigned a[4][4], b[4][2];
#pragma unroll
        for (int fm = 0; fm < 4; fm++) {
            int mb = wm * 64 + fm * 16;
            a[fm][0] = As[kh + tig][mb + gid];
            a[fm][1] = As[kh + tig][mb + gid + 8];
            a[fm][2] = As[kh + tig + 4][mb + gid];
            a[fm][3] = As[kh + tig + 4][mb + gid + 8];
        }
#pragma unroll
        for (int fn = 0; fn < 4; fn++) {
            int nb = wn * 32 + fn * 8;
            b[fn][0] = Bs[kh + tig][nb + gid];
            b[fn][1] = Bs[kh + tig + 4][nb + gid];
        }
#pragma unroll
        for (int fm = 0; fm < 4; fm++)
#pragma unroll
            for (int fn = 0; fn < 4; fn++) mma8(acc[fm][fn], a[fm], b[fn]);
    }
}

// ------------------------- generic tf32 GEMM (CTA 128x128) -------------------------
// mode: 0 store, 1 +=, 2 atomicAdd
__device__ __forceinline__ void gemm128(
    const float* __restrict__ A, const float* __restrict__ B, float* __restrict__ C,
    int m0, int n0, int K, int lda, int ldb, int ldc,
    bool transA, bool transB, int mode)
{
    __shared__ __align__(16) unsigned As[2][16][SSTR];
    __shared__ __align__(16) unsigned Bs[2][16][SSTR];
    const int tid = threadIdx.x;
    const int lane = tid & 31, warp = tid >> 5;
    const int wm = warp >> 2, wn = warp & 3;
    const int gid = lane >> 2, tig = lane & 3;

    float acc[4][4][4];
#pragma unroll
    for (int i = 0; i < 4; i++)
#pragma unroll
        for (int j = 0; j < 4; j++)
#pragma unroll
            for (int l = 0; l < 4; l++) acc[i][j][l] = 0.0f;

    float4 ar[2], br[2];
    auto fetchA = [&](int k0) {
#pragma unroll
        for (int s = 0; s < 2; s++) {
            int lin = tid + 256 * s;
            if (!transA) {
                int m = lin >> 2, kq = (lin & 3) * 4;
                ar[s] = *(const float4*)(A + (long)(m0 + m) * lda + (k0 + kq));
            } else {
                int k = lin >> 5, m4 = (lin & 31) * 4;
                ar[s] = *(const float4*)(A + (long)(k0 + k) * lda + (m0 + m4));
            }
        }
    };
    auto fetchB = [&](int k0) {
#pragma unroll
        for (int s = 0; s < 2; s++) {
            int lin = tid + 256 * s;
            if (transB) {
                int n = lin >> 2, kq = (lin & 3) * 4;
                br[s] = *(const float4*)(B + (long)(n0 + n) * ldb + (k0 + kq));
            } else {
                int k = lin >> 5, n4 = (lin & 31) * 4;
                br[s] = *(const float4*)(B + (long)(k0 + k) * ldb + (n0 + n4));
            }
        }
    };
    auto storeA = [&](int buf) {
#pragma unroll
        for (int s = 0; s < 2; s++) {
            int lin = tid + 256 * s;
            if (!transA) {
                int m = lin >> 2, kq = (lin & 3) * 4;
                As[buf][kq + 0][m] = f2tf(ar[s].x);
                As[buf][kq + 1][m] = f2tf(ar[s].y);
                As[buf][kq + 2][m] = f2tf(ar[s].z);
                As[buf][kq + 3][m] = f2tf(ar[s].w);
            } else {
                int k = lin >> 5, m4 = (lin & 31) * 4;
                uint4 u = {f2tf(ar[s].x), f2tf(ar[s].y), f2tf(ar[s].z), f2tf(ar[s].w)};
                *(uint4*)&As[buf][k][m4] = u;
            }
        }
    };
    auto storeB = [&](int buf) {
#pragma unroll
        for (int s = 0; s < 2; s++) {
            int lin = tid + 256 * s;
            if (transB) {
                int n = lin >> 2, kq = (lin & 3) * 4;
                Bs[buf][kq + 0][n] = f2tf(br[s].x);
                Bs[buf][kq + 1][n] = f2tf(br[s].y);
                Bs[buf][kq + 2][n] = f2tf(br[s].z);
                Bs[buf][kq + 3][n] = f2tf(br[s].w);
            } else {
                int k = lin >> 5, n4 = (lin & 31) * 4;
                uint4 u = {f2tf(br[s].x), f2tf(br[s].y), f2tf(br[s].z), f2tf(br[s].w)};
                *(uint4*)&Bs[buf][k][n4] = u;
            }
        }
    };

    const int nk = K >> 4;
    fetchA(0); fetchB(0); storeA(0); storeB(0);
    __syncthreads();
    for (int t = 0; t < nk; t++) {
        const int cur = t & 1;
        if (t + 1 < nk) { fetchA((t + 1) << 4); fetchB((t + 1) << 4); }
        mma_block(As[cur], Bs[cur], acc, wm, wn, gid, tig);
        if (t + 1 < nk) { storeA(cur ^ 1); storeB(cur ^ 1); }
        __syncthreads();
    }

#pragma unroll
    for (int fm = 0; fm < 4; fm++) {
        int r0 = m0 + wm * 64 + fm * 16 + gid;
#pragma unroll
        for (int fn = 0; fn < 4; fn++) {
            int cc = n0 + wn * 32 + fn * 8 + 2 * tig;
            float* p0 = C + (long)r0 * ldc + cc;
            float* p1 = C + (long)(r0 + 8) * ldc + cc;
            if (mode == 0) {
                p0[0] = acc[fm][fn][0]; p0[1] = acc[fm][fn][1];
                p1[0] = acc[fm][fn][2]; p1[1] = acc[fm][fn][3];
            } else if (mode == 1) {
                p0[0] += acc[fm][fn][0]; p0[1] += acc[fm][fn][1];
                p1[0] += acc[fm][fn][2]; p1[1] += acc[fm][fn][3];
            } else {
                atomicAdd(p0, acc[fm][fn][0]); atomicAdd(p0 + 1, acc[fm][fn][1]);
                atomicAdd(p1, acc[fm][fn][2]); atomicAdd(p1 + 1, acc[fm][fn][3]);
            }
        }
    }
}

// ------------------------- helpers -------------------------
__device__ __forceinline__ float sigmoidf_(float x) { return 1.0f / (1.0f + expf(-x)); }
__device__ __forceinline__ float warp_sum(float v)
{
#pragma unroll
    for (int o = 16; o > 0; o >>= 1) v += __shfl_xor_sync(0xffffffffu, v, o);
    return v;
}

// ------------------------- kernels -------------------------
__global__ void k_initW(const float* __restrict__ w0, const float* __restrict__ w1,
                        const float* __restrict__ w2)
{
    int i = blockIdx.x * blockDim.x + threadIdx.x;
    if (i < FHN * FDIM * FDIM) { g_W0[i] = w0[i]; g_W1[i] = w1[i]; g_W2[i] = w2[i]; }
}

__global__ __launch_bounds__(256) void k_gemm_qkv(const float* __restrict__ x,
                                                  const float* __restrict__ Wqkv)
{
    gemm128(x, Wqkv, g_qkv, blockIdx.y * 128, blockIdx.x * 128,
            DIM, DIM, DIM, 3 * DIM, false, true, 0);
}

__global__ __launch_bounds__(128) void k_lr(const float* __restrict__ x,
                                            const float* __restrict__ Wlr,
                                            const float* __restrict__ blr)
{
    __shared__ __align__(16) float sx[DIM];
    int s = blockIdx.x;
    for (int i = threadIdx.x; i < DIM; i += 128) sx[i] = x[(long)s * DIM + i];
    __syncthreads();
    int w = threadIdx.x >> 5, lane = threadIdx.x & 31;
    for (int j = w; j < 12; j += 4) {
        float sum = 0.0f;
        for (int d = lane; d < DIM; d += 32) sum += sx[d] * Wlr[(long)j * DIM + d];
        sum = warp_sum(sum);
        if (lane == 0) {
            float v = sum + blr[j] + BASE_LR_INV;
            g_lrbuf[s * 12 + j] = (v > 20.0f) ? v : log1pf(expf(v));
        }
    }
}

// RMSNorm(q,k) + fw inputs + fv + RoPE — float4 vectorized
__global__ __launch_bounds__(256) void k_post(const float* __restrict__ qnw,
                                              const float* __restrict__ knw,
                                              const float* __restrict__ qks,
                                              const float* __restrict__ qko)
{
    __shared__ __align__(16) float s_q[DIM];
    __shared__ __align__(16) float s_k[DIM];
    __shared__ __align__(16) float s_cs[32];
    __shared__ __align__(16) float s_sn[32];
    __shared__ float s_w2[8][2];
    __shared__ float s_hq[8], s_hk[8];
    __shared__ float s_fin[2];

    int s = blockIdx.x, t = threadIdx.x, lane = t & 31, w = t >> 5;
    const float* qrow = g_qkv + (long)s * 3072;

    if (t < 32) {
        double inv = exp(-((double)(2 * t) / 64.0) * log(500000.0));
        double a = (double)s * inv;
        const double tw = 6.283185307179586476925286766559;
        a -= floor(a / tw) * tw;
        s_cs[t] = (float)cos(a);
        s_sn[t] = (float)sin(a);
    }

    int d = 4 * t;
    float4 q4 = *(const float4*)(qrow + d);
    float4 k4 = *(const float4*)(qrow + DIM + d);
    float4 v4 = *(const float4*)(qrow + 2 * DIM + d);

    float sq = q4.x * q4.x + q4.y * q4.y + q4.z * q4.z + q4.w * q4.w;
    float sk = k4.x * k4.x + k4.y * k4.y + k4.z * k4.z + k4.w * k4.w;
    sq = warp_sum(sq); sk = warp_sum(sk);
    if (lane == 0) { s_w2[w][0] = sq; s_w2[w][1] = sk; }
    __syncthreads();
    if (t < 2) {
        float a = 0.0f;
#pragma unroll
        for (int i = 0; i < 8; i++) a += s_w2[i][t];
        s_fin[t] = a;
    }
    __syncthreads();
    float rq = rsqrtf(s_fin[0] / 1024.0f + 1e-5f);
    float rk = rsqrtf(s_fin[1] / 1024.0f + 1e-5f);

    float4 qw4 = *(const float4*)(qnw + d);
    float4 kw4 = *(const float4*)(knw + d);
    float qn[4] = {q4.x * rq * qw4.x, q4.y * rq * qw4.y, q4.z * rq * qw4.z, q4.w * rq * qw4.w};
    float kn[4] = {k4.x * rk * kw4.x, k4.y * rk * kw4.y, k4.z * rk * kw4.z, k4.w * rk * kw4.w};
    *(float4*)&s_q[d] = make_float4(qn[0], qn[1], qn[2], qn[3]);
    *(float4*)&s_k[d] = make_float4(kn[0], kn[1], kn[2], kn[3]);

    float4 qsA = *(const float4*)(qks + 2 * d);
    float4 qsB = *(const float4*)(qks + 2 * d + 4);
    float4 qoA = *(const float4*)(qko + 2 * d);
    float4 qoB = *(const float4*)(qko + 2 * d + 4);
    float scq[4] = {qsA.x, qsA.z, qsB.x, qsB.z};
    float sck[4] = {qsA.y, qsA.w, qsB.y, qsB.w};
    float ofq[4] = {qoA.x, qoA.z, qoB.x, qoB.z};
    float ofk[4] = {qoA.y, qoA.w, qoB.y, qoB.w};

    float fq[4], fk[4], fv[4];
    float sqq = 0.0f, skk = 0.0f;
    float vvv[4] = {v4.x, v4.y, v4.z, v4.w};
#pragma unroll
    for (int j = 0; j < 4; j++) {
        fq[j] = qn[j] * sigmoidf_(qn[j]) * scq[j] + ofq[j];
        fk[j] = kn[j] * sigmoidf_(kn[j]) * sck[j] + ofk[j];
        fv[j] = vvv[j] * sigmoidf_(vvv[j]);
        sqq += fq[j] * fq[j];
        skk += fk[j] * fk[j];
    }
    *(float4*)&g_fv[(long)s * DIM + d] = make_float4(fv[0], fv[1], fv[2], fv[3]);

    sqq = warp_sum(sqq); skk = warp_sum(skk);
    if (lane == 0) { s_hq[w] = sqq; s_hk[w] = skk; }
    __syncthreads();
    float rfq = rsqrtf(s_hq[w & ~1] + s_hq[w | 1] + 1e-6f);
    float rfk = rsqrtf(s_hk[w & ~1] + s_hk[w | 1] + 1e-6f);
#pragma unroll
    for (int j = 0; j < 4; j++) { fq[j] *= rfq; fk[j] *= rfk; }
    *(float4*)&g_fq[(long)s * DIM + d] = make_float4(fq[0], fq[1], fq[2], fq[3]);
    *(float4*)&g_fk[(long)s * DIM + d] = make_float4(fk[0], fk[1], fk[2], fk[3]);

    int r = d & 63, ip = d & 31;
    float4 cs = *(float4*)&s_cs[ip];
    float4 sn = *(float4*)&s_sn[ip];
    float4 xq = *(float4*)&s_q[d], xpq = *(float4*)&s_q[d ^ 32];
    float4 xk = *(float4*)&s_k[d], xpk = *(float4*)&s_k[d ^ 32];
    float sgn = (r < 32) ? -1.0f : 1.0f;
    *(float4*)&g_qr[(long)s * DIM + d] = make_float4(
        xq.x * cs.x + sgn * xpq.x * sn.x, xq.y * cs.y + sgn * xpq.y * sn.y,
        xq.z * cs.z + sgn * xpq.z * sn.z, xq.w * cs.w + sgn * xpq.w * sn.w);
    *(float4*)&g_kr[(long)s * DIM + d] = make_float4(
        xk.x * cs.x + sgn * xpk.x * sn.x, xk.y * cs.y + sgn * xpk.y * sn.y,
        xk.z * cs.z + sgn * xpk.z * sn.z, xk.w * cs.w + sgn * xpk.w * sn.w);
}

// TTT stage 1: gk,hk,qg,qm,dh GEMMs + W1 snapshot (z = h*6+op)
__global__ __launch_bounds__(256) void k_ttt1(int c)
{
    int z = blockIdx.z;
    int h = z / 6, op = z - h * 6;
    if (op == 5) {
        int cta = blockIdx.y * 2 + blockIdx.x;
        const float4* src = (const float4*)(g_W1 + h * FDIM * FDIM);
        float4* dst = (float4*)(g_W1c + ((long)c * FHN + h) * FDIM * FDIM);
#pragma unroll
        for (int j = 0; j < 4; j++) {
            int idx = j * 4096 + cta * 256 + threadIdx.x;
            dst[idx] = src[idx];
        }
        return;
    }
    long choff = (long)c * CSZ * DIM + h * FDIM;
    const float* A; const float* B; float* Cp; bool tb = true;
    switch (op) {
        case 0: A = g_fk + choff; B = g_W0 + h * FDIM * FDIM; Cp = g_gk + (long)h * CSZ * FDIM; break;
        case 1: A = g_fk + choff; B = g_W2 + h * FDIM * FDIM; Cp = g_hk + (long)h * CSZ * FDIM; break;
        case 2: A = g_fq + choff; B = g_W0 + h * FDIM * FDIM; Cp = g_qg + (long)h * CSZ * FDIM; break;
        case 3: A = g_fq + choff; B = g_W2 + h * FDIM * FDIM; Cp = g_qm + (long)h * CSZ * FDIM; break;
        default: A = g_fv + choff; B = g_W1 + h * FDIM * FDIM;
                Cp = g_dh + (long)h * CSZ * FDIM; tb = false; break;
    }
    gemm128(A, B, Cp, blockIdx.y * 128, blockIdx.x * 128, FDIM, DIM, FDIM, FDIM, false, tb, 0);
}

// TTT stage 2: elementwise activations / lr scaling — float4 vectorized
__global__ __launch_bounds__(256) void k_ttt2(int c)
{
    long idx = ((long)blockIdx.x * 256 + threadIdx.x) * 4;
    int h = (int)(idx >> 18);
    int rem = (int)(idx & 262143);
    int t = rem >> 8;
    int e = rem & 255;
    int sg = c * CSZ + t;
    float l0 = g_lrbuf[sg * 12 + h];
    float l1 = g_lrbuf[sg * 12 + 4 + h];
    float l2 = g_lrbuf[sg * 12 + 8 + h];
    float4 gk4 = *(const float4*)&g_gk[idx];
    float4 hk4 = *(const float4*)&g_hk[idx];
    float4 dh4 = *(const float4*)&g_dh[idx];
    float4 qg4 = *(const float4*)&g_qg[idx];
    float4 qm4 = *(const float4*)&g_qm[idx];
    float4 fv4 = *(const float4*)&g_fv[(long)sg * DIM + h * FDIM + e];
    float gk[4] = {gk4.x, gk4.y, gk4.z, gk4.w};
    float hk[4] = {hk4.x, hk4.y, hk4.z, hk4.w};
    float dh[4] = {dh4.x, dh4.y, dh4.z, dh4.w};
    float qg[4] = {qg4.x, qg4.y, qg4.z, qg4.w};
    float qm[4] = {qm4.x, qm4.y, qm4.z, qm4.w};
    float fv[4] = {fv4.x, fv4.y, fv4.z, fv4.w};
    float hq[4], hid[4], dgk[4], dhk[4], vl1[4];
#pragma unroll
    for (int j = 0; j < 4; j++) {
        float sgm = sigmoidf_(gk[j]);
        float sil = gk[j] * sgm;
        hq[j] = qg[j] * sigmoidf_(qg[j]) * qm[j];
        hid[j] = sil * hk[j];
        float dsil = sgm * (1.0f + gk[j] * (1.0f - sgm));
        dgk[j] = dh[j] * hk[j] * dsil * l0;
        dhk[j] = dh[j] * sil * l2;
        vl1[j] = fv[j] * l1;
    }
    *(float4*)&g_hqa[(long)c * FHN * CSZ * FDIM + idx] = make_float4(hq[0], hq[1], hq[2], hq[3]);
    *(float4*)&g_hid[idx] = make_float4(hid[0], hid[1], hid[2], hid[3]);
    *(float4*)&g_dgk[idx] = make_float4(dgk[0], dgk[1], dgk[2], dgk[3]);
    *(float4*)&g_dhk[idx] = make_float4(dhk[0], dhk[1], dhk[2], dhk[3]);
    *(float4*)&g_vl1[idx] = make_float4(vl1[0], vl1[1], vl1[2], vl1[3]);
}

// TTT stage 4: rank-CSZ weight updates, split-K 8x with atomic accumulate
__global__ __launch_bounds__(256) void k_ttt4(int c)
{
    int z = blockIdx.z;
    int h = z / 24;
    int r = z - h * 24;
    int op = r >> 3, sl = r & 7;
    long koff = (long)c * CSZ * DIM + h * FDIM;
    const float* A; const float* B; float* Cp; int lda, ldb;
    switch (op) {
        case 0: A = g_vl1 + (long)h * CSZ * FDIM; B = g_hid + (long)h * CSZ * FDIM;
                Cp = g_W1 + h * FDIM * FDIM; lda = FDIM; ldb = FDIM; break;
        case 1: A = g_dgk + (long)h * CSZ * FDIM; B = g_fk + koff;
                Cp = g_W0 + h * FDIM * FDIM; lda = FDIM; ldb = DIM; break;
        default: A = g_dhk + (long)h * CSZ * FDIM; B = g_fk + koff;
                Cp = g_W2 + h * FDIM * FDIM; lda = FDIM; ldb = DIM; break;
    }
    A += (long)sl * 128 * lda;
    B += (long)sl * 128 * ldb;
    gemm128(A, B, Cp, blockIdx.y * 128, blockIdx.x * 128, 128, lda, ldb, FDIM, true, false, 2);
}

// Deferred TTT stage 3, one chunk (runs on side stream in loop shadow)
__global__ __launch_bounds__(256) void k_ttt3c(int c)
{
    int h = blockIdx.z;
    gemm128(g_hqa + ((long)c * FHN + h) * CSZ * FDIM,
            g_W1c + ((long)c * FHN + h) * FDIM * FDIM,
            g_ttt + (long)c * CSZ * DIM + h * FDIM,
            blockIdx.y * 128, blockIdx.x * 128, FDIM, FDIM, FDIM, DIM, false, true, 0);
}

// ------------------------- tf32 flash attention -------------------------
#define SQSTR 68
#define SKSTR 68
#define SVSTR 72
#define ATTN_SMEM ((128 * SQSTR + 64 * SKSTR + 64 * SVSTR) * 4)

__global__ __launch_bounds__(256) void k_attn()
{
    extern __shared__ __align__(16) float sm[];
    float* sQP = sm;
    unsigned* sK = (unsigned*)(sm + 128 * SQSTR);
    unsigned* sV = (unsigned*)(sm + 128 * SQSTR + 64 * SKSTR);

    const int h = blockIdx.y, qt = blockIdx.x;
    const int p0 = qt * 128;
    const int tid = threadIdx.x;
    const int lane = tid & 31, warp = tid >> 5;
    const int gid = lane >> 2, tig = lane & 3;

#pragma unroll
    for (int s = 0; s < 8; s++) {
        int lin = tid + 256 * s;
        int r = lin >> 4, c4 = (lin & 15) * 4;
        *(float4*)&sQP[r * SQSTR + c4] =
            *(const float4*)&g_qr[(long)(p0 + r) * DIM + h * HDIM + c4];
    }
    __syncthreads();

    const int rq = warp * 16 + gid;
    unsigned qa[8][4];
#pragma unroll
    for (int kb = 0; kb < 8; kb++) {
        qa[kb][0] = f2tf(0.125f * sQP[rq * SQSTR + kb * 8 + tig]);
        qa[kb][1] = f2tf(0.125f * sQP[(rq + 8) * SQSTR + kb * 8 + tig]);
        qa[kb][2] = f2tf(0.125f * sQP[rq * SQSTR + kb * 8 + tig + 4]);
        qa[kb][3] = f2tf(0.125f * sQP[(rq + 8) * SQSTR + kb * 8 + tig + 4]);
    }

    float o[8][4];
#pragma unroll
    for (int fn = 0; fn < 8; fn++)
#pragma unroll
        for (int j = 0; j < 4; j++) o[fn][j] = 0.0f;
    float mrow0 = -1e30f, mrow1 = -1e30f, lsum0 = 0.0f, lsum1 = 0.0f;

    const int ktlo = (qt >= 8) ? 2 * qt - 16 : 0;
    const int kthi = 2 * qt + 1;
    const int prow0 = p0 + warp * 16 + gid;
    const int prow1 = prow0 + 8;

    for (int kt = ktlo; kt <= kthi; kt++) {
        __syncthreads();
#pragma unroll
        for (int s = 0; s < 4; s++) {
            int lin = tid + 256 * s;
            int r = lin >> 4, c4 = (lin & 15) * 4;
            float4 kv = *(const float4*)&g_kr[(long)(kt * 64 + r) * DIM + h * HDIM + c4];
            uint4 ku = {f2tf(kv.x), f2tf(kv.y), f2tf(kv.z), f2tf(kv.w)};
            *(uint4*)&sK[r * SKSTR + c4] = ku;
            float4 vv = *(const float4*)&g_qkv[(long)(kt * 64 + r) * 3072 + 2048 + h * HDIM + c4];
            uint4 vu = {f2tf(vv.x), f2tf(vv.y), f2tf(vv.z), f2tf(vv.w)};
            *(uint4*)&sV[r * SVSTR + c4] = vu;
        }
        __syncthreads();

        float sc[8][4];
#pragma unroll
        for (int fn = 0; fn < 8; fn++)
#pragma unroll
            for (int j = 0; j < 4; j++) sc[fn][j] = 0.0f;
#pragma unroll
        for (int kb = 0; kb < 8; kb++) {
#pragma unroll
            for (int fn = 0; fn < 8; fn++) {
                unsigned b[2];
                b[0] = sK[(fn * 8 + gid) * SKSTR + kb * 8 + tig];
                b[1] = sK[(fn * 8 + gid) * SKSTR + kb * 8 + tig + 4];
                mma8(sc[fn], qa[kb], b);
            }
        }
#pragma unroll
        for (int fn = 0; fn < 8; fn++) {
            int g0 = kt * 64 + fn * 8 + 2 * tig;
            int g1 = g0 + 1;
            sc[fn][0] = (g0 > prow0 - 1024 && g0 <= prow0) ? sc[fn][0] : -1e30f;
            sc[fn][1] = (g1 > prow0 - 1024 && g1 <= prow0) ? sc[fn][1] : -1e30f;
            sc[fn][2] = (g0 > prow1 - 1024 && g0 <= prow1) ? sc[fn][2] : -1e30f;
            sc[fn][3] = (g1 > prow1 - 1024 && g1 <= prow1) ? sc[fn][3] : -1e30f;
        }
        float t0 = -1e30f, t1 = -1e30f;
#pragma unroll
        for (int fn = 0; fn < 8; fn++) {
            t0 = fmaxf(t0, fmaxf(sc[fn][0], sc[fn][1]));
            t1 = fmaxf(t1, fmaxf(sc[fn][2], sc[fn][3]));
        }
#pragma unroll
        for (int off = 1; off < 4; off <<= 1) {
            t0 = fmaxf(t0, __shfl_xor_sync(0xffffffffu, t0, off));
            t1 = fmaxf(t1, __shfl_xor_sync(0xffffffffu, t1, off));
        }
        float mn0 = fmaxf(mrow0, t0), mn1 = fmaxf(mrow1, t1);
        float al0 = expf(mrow0 - mn0), al1 = expf(mrow1 - mn1);
        float mc0 = fmaxf(mn0, -1e20f), mc1 = fmaxf(mn1, -1e20f);
        float rs0 = 0.0f, rs1 = 0.0f;
#pragma unroll
        for (int fn = 0; fn < 8; fn++) {
            sc[fn][0] = expf(sc[fn][0] - mc0);
            sc[fn][1] = expf(sc[fn][1] - mc0);
            sc[fn][2] = expf(sc[fn][2] - mc1);
            sc[fn][3] = expf(sc[fn][3] - mc1);
            rs0 += sc[fn][0] + sc[fn][1];
            rs1 += sc[fn][2] + sc[fn][3];
        }
#pragma unroll
        for (int off = 1; off < 4; off <<= 1) {
            rs0 += __shfl_xor_sync(0xffffffffu, rs0, off);
            rs1 += __shfl_xor_sync(0xffffffffu, rs1, off);
        }
        lsum0 = lsum0 * al0 + rs0;
        lsum1 = lsum1 * al1 + rs1;
        mrow0 = mn0; mrow1 = mn1;
#pragma unroll
        for (int fn = 0; fn < 8; fn++) {
            o[fn][0] *= al0; o[fn][1] *= al0;
            o[fn][2] *= al1; o[fn][3] *= al1;
        }
        const int rp = warp * 16 + gid;
#pragma unroll
        for (int fn = 0; fn < 8; fn++) {
            sQP[rp * SQSTR + fn * 8 + 2 * tig]           = sc[fn][0];
            sQP[rp * SQSTR + fn * 8 + 2 * tig + 1]       = sc[fn][1];
            sQP[(rp + 8) * SQSTR + fn * 8 + 2 * tig]     = sc[fn][2];
            sQP[(rp + 8) * SQSTR + fn * 8 + 2 * tig + 1] = sc[fn][3];
        }
        __syncwarp();
#pragma unroll
        for (int kb = 0; kb < 8; kb++) {
            unsigned pa[4];
            pa[0] = f2tf(sQP[rp * SQSTR + kb * 8 + tig]);
            pa[1] = f2tf(sQP[(rp + 8) * SQSTR + kb * 8 + tig]);
            pa[2] = f2tf(sQP[rp * SQSTR + kb * 8 + tig + 4]);
            pa[3] = f2tf(sQP[(rp + 8) * SQSTR + kb * 8 + tig + 4]);
#pragma unroll
            for (int fn = 0; fn < 8; fn++) {
                unsigned b[2];
                b[0] = sV[(kb * 8 + tig) * SVSTR + fn * 8 + gid];
                b[1] = sV[(kb * 8 + tig + 4) * SVSTR + fn * 8 + gid];
                mma8(o[fn], pa, b);
            }
        }
        __syncwarp();
    }

    float inv0 = 1.0f / lsum0, inv1 = 1.0f / lsum1;
#pragma unroll
    for (int fn = 0; fn < 8; fn++) {
        int cc = h * HDIM + fn * 8 + 2 * tig;
        g_ao[(long)prow0 * DIM + cc]     = o[fn][0] * inv0;
        g_ao[(long)prow0 * DIM + cc + 1] = o[fn][1] * inv0;
        g_ao[(long)prow1 * DIM + cc]     = o[fn][2] * inv1;
        g_ao[(long)prow1 * DIM + cc + 1] = o[fn][3] * inv1;
    }
}

// TTT rmsnorm + add into g_ao, one chunk of rows (runs on s2 after ttt3c(c))
__global__ __launch_bounds__(256) void k_comb_c(int c, const float* __restrict__ tnw)
{
    __shared__ float s_h[8];
    int s = c * CSZ + blockIdx.x, t = threadIdx.x, lane = t & 31, w = t >> 5;
    int d = 4 * t;
    float4 v4 = *(const float4*)&g_ttt[(long)s * DIM + d];
    float p = v4.x * v4.x + v4.y * v4.y + v4.z * v4.z + v4.w * v4.w;
    p = warp_sum(p);
    if (lane == 0) s_h[w] = p;
    __syncthreads();
    float r = rsqrtf((s_h[w & ~1] + s_h[w | 1]) / 256.0f + 1e-5f);
    float4 w4 = *(const float4*)&tnw[d & 255];
    float4 a4 = *(float4*)&g_ao[(long)s * DIM + d];
    a4.x += v4.x * r * w4.x; a4.y += v4.y * r * w4.y;
    a4.z += v4.z * r * w4.z; a4.w += v4.w * r * w4.w;
    *(float4*)&g_ao[(long)s * DIM + d] = a4;
}

__global__ __launch_bounds__(256) void k_gemm_out(const float* __restrict__ Wo,
                                                 float* __restrict__ out)
{
    gemm128(g_ao, Wo, out, blockIdx.y * 128, blockIdx.x * 128,
            DIM, DIM, DIM, DIM, false, true, 0);
}

// ------------------------- launch -------------------------
extern "C" void kernel_launch(void* const* d_in, const int* in_sizes, int n_in,
                              void* d_out, int out_size)
{
    const float* x    = (const float*)d_in[0];
    const float* Wqkv = (const float*)d_in[1];
    const float* qnw  = (const float*)d_in[2];
    const float* knw  = (const float*)d_in[3];
    const float* Wo   = (const float*)d_in[4];
    const float* w0   = (const float*)d_in[5];
    const float* w1   = (const float*)d_in[6];
    const float* w2   = (const float*)d_in[7];
    const float* Wlr  = (const float*)d_in[8];
    const float* blr  = (const float*)d_in[9];
    const float* qks  = (const float*)d_in[10];
    const float* qko  = (const float*)d_in[11];
    const float* tnw  = (const float*)d_in[12];
    float* out = (float*)d_out;

    cudaFuncSetAttribute(k_attn, cudaFuncAttributeMaxDynamicSharedMemorySize, ATTN_SMEM);

    cudaStream_t s2 = g_sc.s2;

    if (g_sc.ok) {
        cudaEventRecord(g_sc.e0, 0);
        cudaStreamWaitEvent(s2, g_sc.e0, 0);
        k_initW<<<1024, 256, 0, s2>>>(w0, w1, w2);
        k_lr<<<4096, 128, 0, s2>>>(x, Wlr, blr);
        cudaEventRecord(g_sc.e1, s2);

        k_gemm_qkv<<<dim3(24, 32), 256>>>(x, Wqkv);
        k_post<<<4096, 256>>>(qnw, knw, qks, qko);

        cudaEventRecord(g_sc.e2, 0);
        cudaStreamWaitEvent(s2, g_sc.e2, 0);
        k_attn<<<dim3(32, NHEAD), 256, ATTN_SMEM, s2>>>();

        cudaStreamWaitEvent(0, g_sc.e1, 0);
        for (int c = 0; c < NCH; c++) {
            k_ttt1<<<dim3(2, 8, 24), 256>>>(c);
            k_ttt2<<<1024, 256>>>(c);
            // ttt3 + comb for this chunk on s2 (attn precedes them in-stream)
            cudaEventRecord(g_sc.ec[c], 0);
            cudaStreamWaitEvent(s2, g_sc.ec[c], 0);
            k_ttt3c<<<dim3(2, 8, 4), 256, 0, s2>>>(c);
            k_comb_c<<<1024, 256, 0, s2>>>(c, tnw);
            k_ttt4<<<dim3(2, 2, 96), 256>>>(c);
        }
        cudaEventRecord(g_sc.e3, s2);

        cudaStreamWaitEvent(0, g_sc.e3, 0);
        k_gemm_out<<<dim3(8, 32), 256>>>(Wo, out);
    } else {
        k_initW<<<1024, 256>>>(w0, w1, w2);
        k_gemm_qkv<<<dim3(24, 32), 256>>>(x, Wqkv);
        k_lr<<<4096, 128>>>(x, Wlr, blr);
        k_post<<<4096, 256>>>(qnw, knw, qks, qko);
        for (int c = 0; c < NCH; c++) {
            k_ttt1<<<dim3(2, 8, 24), 256>>>(c);
            k_ttt2<<<1024, 256>>>(c);
            k_ttt3c<<<dim3(2, 8, 4), 256>>>(c);
            k_ttt4<<<dim3(2, 2, 96), 256>>>(c);
        }
        k_attn<<<dim3(32, NHEAD), 256, ATTN_SMEM>>>();
        for (int c = 0; c < NCH; c++) k_comb_c<<<1024, 256>>>(c, tnw);
        k_gemm_out<<<dim3(8, 32), 256>>>(Wo, out);
    }
}